// round 1
// baseline (speedup 1.0000x reference)
#include <cuda_runtime.h>
#include <cuda_bf16.h>
#include <cstdint>
#include <cstddef>

// ---------------- problem constants ----------------
#define BB   32
#define TT   1024
#define NN   77
#define DD   512
#define LL   256
#define HH   8
#define HD   64
#define M_X  (BB*TT)          // 32768 rows of x
#define M_XF (BB*NN)          // 2464 rows of xf

// ---------------- scratch (static device, no allocation) ----------------
__device__ float  g_q[(size_t)M_X * DD];    // 64 MB
__device__ float  g_k[(size_t)M_XF * DD];   // 4.8 MB
__device__ float  g_v[(size_t)M_XF * DD];   // 4.8 MB
__device__ float2 g_stats_x[M_X];
__device__ float2 g_stats_xf[M_XF];

// ---------------- helpers ----------------
__device__ __forceinline__ uint32_t f2tf32(float x) {
    uint32_t u;
    asm("cvt.rna.tf32.f32 %0, %1;" : "=r"(u) : "f"(x));
    return u;
}
__device__ __forceinline__ float f2tf32f(float x) { return __uint_as_float(f2tf32(x)); }

__device__ __forceinline__ void mma_tf32(float* c,
                                         uint32_t a0, uint32_t a1, uint32_t a2, uint32_t a3,
                                         uint32_t b0, uint32_t b1) {
    asm volatile(
        "mma.sync.aligned.m16n8k8.row.col.f32.tf32.tf32.f32 "
        "{%0,%1,%2,%3}, {%4,%5,%6,%7}, {%8,%9}, {%0,%1,%2,%3};"
        : "+f"(c[0]), "+f"(c[1]), "+f"(c[2]), "+f"(c[3])
        : "r"(a0), "r"(a1), "r"(a2), "r"(a3), "r"(b0), "r"(b1));
}

// ---------------- K1: per-row LayerNorm stats ----------------
__global__ __launch_bounds__(256) void stats_kernel(const float* __restrict__ X,
                                                    float2* __restrict__ stats,
                                                    int rows, int K) {
    int row = blockIdx.x * 8 + (threadIdx.x >> 5);
    if (row >= rows) return;
    int lane = threadIdx.x & 31;
    const float4* p = (const float4*)(X + (size_t)row * K);
    int nf4 = K >> 2;
    float s = 0.f, sq = 0.f;
    for (int i = lane; i < nf4; i += 32) {
        float4 v = p[i];
        s  += v.x + v.y + v.z + v.w;
        sq += v.x*v.x + v.y*v.y + v.z*v.z + v.w*v.w;
    }
    #pragma unroll
    for (int off = 16; off > 0; off >>= 1) {
        s  += __shfl_xor_sync(0xffffffffu, s,  off);
        sq += __shfl_xor_sync(0xffffffffu, sq, off);
    }
    if (lane == 0) {
        float mean = s / (float)K;
        float var  = sq / (float)K - mean * mean;
        var = fmaxf(var, 0.f);
        stats[row] = make_float2(mean, rsqrtf(var + 1e-5f));
    }
}

// ---------------- K2: C = LayerNorm_rows(A) @ B + bias  (tf32 mma) ----------------
// A: (M,K) row-major fp32, stats per row, gamma/beta per k-column.
// B: (K,N) row-major fp32.  C: (M,N) row-major fp32.
// Tiles: BM=128, BN=128, BK=16, 256 threads (8 warps as 4m x 2n), warp tile 32x64.
#define GBM 128
#define GBN 128
#define GBK 16
#define A_LD 20     // (20*r + k) % 32 distinct for r<8,k<4 -> conflict-free frag loads
#define B_LD 136    // 136 % 32 == 8  -> (8k + n) distinct  -> conflict-free frag loads

__global__ __launch_bounds__(256) void ln_gemm_kernel(
    const float*  __restrict__ A, const float2* __restrict__ stats,
    const float*  __restrict__ gamma, const float* __restrict__ beta,
    const float*  __restrict__ B, const float* __restrict__ bias,
    float* __restrict__ C, int M, int K, int N)
{
    __shared__ float As[2][GBM][A_LD];
    __shared__ float Bs[2][GBK][B_LD];

    const int tid = threadIdx.x;
    const int m0 = blockIdx.y * GBM;
    const int n0 = blockIdx.x * GBN;

    // loader coords
    const int ar0 = tid >> 2;            // 0..63 ; second slot += 64
    const int ac  = (tid & 3) * 4;       // 0,4,8,12
    const int bk0 = tid >> 5;            // 0..7  ; second slot += 8
    const int bn  = (tid & 31) * 4;      // 0..124

    // compute coords
    const int wid  = tid >> 5;
    const int lane = tid & 31;
    const int wm = wid & 3;              // 0..3
    const int wn = wid >> 2;             // 0..1
    const int g  = lane >> 2;            // 0..7
    const int tg = lane & 3;             // 0..3

    float acc[2][8][4];
    #pragma unroll
    for (int mt = 0; mt < 2; mt++)
        #pragma unroll
        for (int nt = 0; nt < 8; nt++)
            #pragma unroll
            for (int j = 0; j < 4; j++) acc[mt][nt][j] = 0.f;

    const int KT = K / GBK;
    float4 pa[2], pb[2];

    // ---- prolog: load tile 0 ----
    {
        const int k0 = 0;
        float4 gm = *(const float4*)(gamma + k0 + ac);
        float4 bt = *(const float4*)(beta  + k0 + ac);
        #pragma unroll
        for (int i = 0; i < 2; i++) {
            int m = m0 + ar0 + i * 64;
            float4 v = make_float4(0.f, 0.f, 0.f, 0.f);
            if (m < M) {
                v = *(const float4*)(A + (size_t)m * K + k0 + ac);
                float2 st = stats[m];
                v.x = (v.x - st.x) * st.y * gm.x + bt.x;
                v.y = (v.y - st.x) * st.y * gm.y + bt.y;
                v.z = (v.z - st.x) * st.y * gm.z + bt.z;
                v.w = (v.w - st.x) * st.y * gm.w + bt.w;
            }
            pa[i] = v;
            pb[i] = *(const float4*)(B + (size_t)(k0 + bk0 + i * 8) * N + n0 + bn);
        }
        #pragma unroll
        for (int i = 0; i < 2; i++) {
            int r = ar0 + i * 64;
            As[0][r][ac + 0] = f2tf32f(pa[i].x);
            As[0][r][ac + 1] = f2tf32f(pa[i].y);
            As[0][r][ac + 2] = f2tf32f(pa[i].z);
            As[0][r][ac + 3] = f2tf32f(pa[i].w);
            int kr = bk0 + i * 8;
            Bs[0][kr][bn + 0] = f2tf32f(pb[i].x);
            Bs[0][kr][bn + 1] = f2tf32f(pb[i].y);
            Bs[0][kr][bn + 2] = f2tf32f(pb[i].z);
            Bs[0][kr][bn + 3] = f2tf32f(pb[i].w);
        }
    }
    __syncthreads();

    for (int kt = 0; kt < KT; kt++) {
        const int cur = kt & 1;
        const int nxt = cur ^ 1;
        const bool hasNext = (kt + 1 < KT);

        // issue global prefetch for next tile
        if (hasNext) {
            const int k0 = (kt + 1) * GBK;
            float4 gm = *(const float4*)(gamma + k0 + ac);
            float4 bt = *(const float4*)(beta  + k0 + ac);
            #pragma unroll
            for (int i = 0; i < 2; i++) {
                int m = m0 + ar0 + i * 64;
                float4 v = make_float4(0.f, 0.f, 0.f, 0.f);
                if (m < M) {
                    v = *(const float4*)(A + (size_t)m * K + k0 + ac);
                    float2 st = stats[m];
                    v.x = (v.x - st.x) * st.y * gm.x + bt.x;
                    v.y = (v.y - st.x) * st.y * gm.y + bt.y;
                    v.z = (v.z - st.x) * st.y * gm.z + bt.z;
                    v.w = (v.w - st.x) * st.y * gm.w + bt.w;
                }
                pa[i] = v;
                pb[i] = *(const float4*)(B + (size_t)(k0 + bk0 + i * 8) * N + n0 + bn);
            }
        }

        // compute on current buffer
        #pragma unroll
        for (int ks = 0; ks < 2; ks++) {
            const int kk = ks * 8;
            uint32_t afr[2][4];
            #pragma unroll
            for (int mt = 0; mt < 2; mt++) {
                int rb = wm * 32 + mt * 16;
                afr[mt][0] = __float_as_uint(As[cur][rb + g    ][kk + tg    ]);
                afr[mt][1] = __float_as_uint(As[cur][rb + 8 + g][kk + tg    ]);
                afr[mt][2] = __float_as_uint(As[cur][rb + g    ][kk + 4 + tg]);
                afr[mt][3] = __float_as_uint(As[cur][rb + 8 + g][kk + 4 + tg]);
            }
            #pragma unroll
            for (int nt = 0; nt < 8; nt++) {
                int cb = wn * 64 + nt * 8 + g;
                uint32_t b0 = __float_as_uint(Bs[cur][kk + tg    ][cb]);
                uint32_t b1 = __float_as_uint(Bs[cur][kk + 4 + tg][cb]);
                mma_tf32(acc[0][nt], afr[0][0], afr[0][1], afr[0][2], afr[0][3], b0, b1);
                mma_tf32(acc[1][nt], afr[1][0], afr[1][1], afr[1][2], afr[1][3], b0, b1);
            }
        }

        // store prefetched regs into the other buffer
        if (hasNext) {
            #pragma unroll
            for (int i = 0; i < 2; i++) {
                int r = ar0 + i * 64;
                As[nxt][r][ac + 0] = f2tf32f(pa[i].x);
                As[nxt][r][ac + 1] = f2tf32f(pa[i].y);
                As[nxt][r][ac + 2] = f2tf32f(pa[i].z);
                As[nxt][r][ac + 3] = f2tf32f(pa[i].w);
                int kr = bk0 + i * 8;
                Bs[nxt][kr][bn + 0] = f2tf32f(pb[i].x);
                Bs[nxt][kr][bn + 1] = f2tf32f(pb[i].y);
                Bs[nxt][kr][bn + 2] = f2tf32f(pb[i].z);
                Bs[nxt][kr][bn + 3] = f2tf32f(pb[i].w);
            }
        }
        __syncthreads();
    }

    // ---- epilogue: += bias, store ----
    #pragma unroll
    for (int mt = 0; mt < 2; mt++) {
        int r0 = m0 + wm * 32 + mt * 16 + g;
        #pragma unroll
        for (int nt = 0; nt < 8; nt++) {
            int col = n0 + wn * 64 + nt * 8 + 2 * tg;
            float bv0 = bias[col], bv1 = bias[col + 1];
            if (r0 < M) {
                float2 o = make_float2(acc[mt][nt][0] + bv0, acc[mt][nt][1] + bv1);
                *(float2*)(C + (size_t)r0 * N + col) = o;
            }
            int r1 = r0 + 8;
            if (r1 < M) {
                float2 o = make_float2(acc[mt][nt][2] + bv0, acc[mt][nt][3] + bv1);
                *(float2*)(C + (size_t)r1 * N + col) = o;
            }
        }
    }
}

// ---------------- K4: fused attention ----------------
// grid = (8 t-tiles, 32 batches), 256 threads (8 warps, warp owns 16 t-rows).
// Per head: stage q (128x64), k/v (80x64, rows 77..79 zeroed) as tf32 in smem;
// S = q k^T via mma; masked softmax in regs; P staged to smem (aliases q); PV via mma.
#define KV_LD 72    // 72%32==8 -> conflict-free fragment loads
#define QS_LD 72
#define PS_LD 84    // 84%32==20 -> row bases {0,20,8,28,16,4,24,12} -> conflict-free
#define SM_KV  (80 * KV_LD)            // floats, one of k_s / v_s
#define SM_QP  (128 * PS_LD)           // q_s (128*72) aliased under p_s (128*84)
#define ATTN_SMEM_FLOATS (2 * SM_KV + SM_QP)
#define ATTN_SMEM_BYTES  (ATTN_SMEM_FLOATS * 4)

__global__ __launch_bounds__(256) void attn_kernel(
    const float* __restrict__ q, const float* __restrict__ k,
    const float* __restrict__ v, float* __restrict__ out)
{
    extern __shared__ float sm[];
    float* k_s = sm;                 // [80][KV_LD]
    float* v_s = sm + SM_KV;         // [80][KV_LD]
    float* q_s = sm + 2 * SM_KV;     // [128][QS_LD]
    float* p_s = sm + 2 * SM_KV;     // [128][PS_LD] (aliases q_s)

    const int b  = blockIdx.y;
    const int t0 = blockIdx.x * 128;
    const int tid  = threadIdx.x;
    const int wid  = tid >> 5;
    const int lane = tid & 31;
    const int g  = lane >> 2;
    const int tg = lane & 3;
    const int rb = wid * 16;         // warp's row base in the 128-tile
    const float scale = 0.125f;      // 1/sqrt(64)

    for (int h = 0; h < HH; h++) {
        __syncthreads();   // previous head's smem reads done

        // ---- stage k_s / v_s (80 rows, zero-pad 77..79) ----
        for (int s = tid; s < 80 * 16; s += 256) {
            int n  = s >> 4;
            int c4 = (s & 15) * 4;
            float4 kv = make_float4(0.f, 0.f, 0.f, 0.f);
            float4 vv = make_float4(0.f, 0.f, 0.f, 0.f);
            if (n < NN) {
                size_t base = (size_t)(b * NN + n) * DD + h * HD + c4;
                kv = *(const float4*)(k + base);
                vv = *(const float4*)(v + base);
            }
            float* kd = k_s + n * KV_LD + c4;
            kd[0] = f2tf32f(kv.x); kd[1] = f2tf32f(kv.y);
            kd[2] = f2tf32f(kv.z); kd[3] = f2tf32f(kv.w);
            float* vd = v_s + n * KV_LD + c4;
            vd[0] = f2tf32f(vv.x); vd[1] = f2tf32f(vv.y);
            vd[2] = f2tf32f(vv.z); vd[3] = f2tf32f(vv.w);
        }
        // ---- stage q_s (128 rows) ----
        for (int s = tid; s < 128 * 16; s += 256) {
            int r  = s >> 4;
            int c4 = (s & 15) * 4;
            float4 qv = *(const float4*)(q + (size_t)(b * TT + t0 + r) * DD + h * HD + c4);
            float* qd = q_s + r * QS_LD + c4;
            qd[0] = f2tf32f(qv.x); qd[1] = f2tf32f(qv.y);
            qd[2] = f2tf32f(qv.z); qd[3] = f2tf32f(qv.w);
        }
        __syncthreads();

        // ---- S = q @ k^T : warp computes 16 x 80 strip, K=64 ----
        float sacc[10][4];
        #pragma unroll
        for (int nt = 0; nt < 10; nt++)
            #pragma unroll
            for (int j = 0; j < 4; j++) sacc[nt][j] = 0.f;

        #pragma unroll
        for (int kk = 0; kk < 8; kk++) {
            const int d = kk * 8;
            uint32_t a0 = __float_as_uint(q_s[(rb + g    ) * QS_LD + d + tg    ]);
            uint32_t a1 = __float_as_uint(q_s[(rb + 8 + g) * QS_LD + d + tg    ]);
            uint32_t a2 = __float_as_uint(q_s[(rb + g    ) * QS_LD + d + 4 + tg]);
            uint32_t a3 = __float_as_uint(q_s[(rb + 8 + g) * QS_LD + d + 4 + tg]);
            #pragma unroll
            for (int nt = 0; nt < 10; nt++) {
                uint32_t b0 = __float_as_uint(k_s[(nt * 8 + g) * KV_LD + d + tg    ]);
                uint32_t b1 = __float_as_uint(k_s[(nt * 8 + g) * KV_LD + d + 4 + tg]);
                mma_tf32(sacc[nt], a0, a1, a2, a3, b0, b1);
            }
        }

        // ---- masked softmax over n (cols >= 77 masked) ----
        float mx0 = -1e30f, mx1 = -1e30f;
        #pragma unroll
        for (int nt = 0; nt < 10; nt++) {
            int c0 = nt * 8 + 2 * tg;
            sacc[nt][0] = (c0     < NN) ? sacc[nt][0] * scale : -1e30f;
            sacc[nt][1] = (c0 + 1 < NN) ? sacc[nt][1] * scale : -1e30f;
            sacc[nt][2] = (c0     < NN) ? sacc[nt][2] * scale : -1e30f;
            sacc[nt][3] = (c0 + 1 < NN) ? sacc[nt][3] * scale : -1e30f;
            mx0 = fmaxf(mx0, fmaxf(sacc[nt][0], sacc[nt][1]));
            mx1 = fmaxf(mx1, fmaxf(sacc[nt][2], sacc[nt][3]));
        }
        mx0 = fmaxf(mx0, __shfl_xor_sync(0xffffffffu, mx0, 1));
        mx0 = fmaxf(mx0, __shfl_xor_sync(0xffffffffu, mx0, 2));
        mx1 = fmaxf(mx1, __shfl_xor_sync(0xffffffffu, mx1, 1));
        mx1 = fmaxf(mx1, __shfl_xor_sync(0xffffffffu, mx1, 2));

        float s0 = 0.f, s1 = 0.f;
        #pragma unroll
        for (int nt = 0; nt < 10; nt++) {
            sacc[nt][0] = __expf(sacc[nt][0] - mx0);
            sacc[nt][1] = __expf(sacc[nt][1] - mx0);
            sacc[nt][2] = __expf(sacc[nt][2] - mx1);
            sacc[nt][3] = __expf(sacc[nt][3] - mx1);
            s0 += sacc[nt][0] + sacc[nt][1];
            s1 += sacc[nt][2] + sacc[nt][3];
        }
        s0 += __shfl_xor_sync(0xffffffffu, s0, 1);
        s0 += __shfl_xor_sync(0xffffffffu, s0, 2);
        s1 += __shfl_xor_sync(0xffffffffu, s1, 1);
        s1 += __shfl_xor_sync(0xffffffffu, s1, 2);
        const float inv0 = 1.0f / s0;
        const float inv1 = 1.0f / s1;

        __syncthreads();   // all warps done reading q_s before p_s overwrites the alias

        // ---- store normalized P (tf32) to smem ----
        #pragma unroll
        for (int nt = 0; nt < 10; nt++) {
            int c0 = nt * 8 + 2 * tg;
            float2 p01 = make_float2(f2tf32f(sacc[nt][0] * inv0), f2tf32f(sacc[nt][1] * inv0));
            float2 p23 = make_float2(f2tf32f(sacc[nt][2] * inv1), f2tf32f(sacc[nt][3] * inv1));
            *(float2*)(p_s + (rb + g    ) * PS_LD + c0) = p01;
            *(float2*)(p_s + (rb + 8 + g) * PS_LD + c0) = p23;
        }
        __syncwarp();

        // ---- Y = P @ V : 16 x 64, K=80 ----
        float yacc[8][4];
        #pragma unroll
        for (int nt = 0; nt < 8; nt++)
            #pragma unroll
            for (int j = 0; j < 4; j++) yacc[nt][j] = 0.f;

        #pragma unroll
        for (int kk = 0; kk < 10; kk++) {
            const int kb = kk * 8;
            uint32_t a0 = __float_as_uint(p_s[(rb + g    ) * PS_LD + kb + tg    ]);
            uint32_t a1 = __float_as_uint(p_s[(rb + 8 + g) * PS_LD + kb + tg    ]);
            uint32_t a2 = __float_as_uint(p_s[(rb + g    ) * PS_LD + kb + 4 + tg]);
            uint32_t a3 = __float_as_uint(p_s[(rb + 8 + g) * PS_LD + kb + 4 + tg]);
            #pragma unroll
            for (int nt = 0; nt < 8; nt++) {
                uint32_t b0 = __float_as_uint(v_s[(kb + tg    ) * KV_LD + nt * 8 + g]);
                uint32_t b1 = __float_as_uint(v_s[(kb + 4 + tg) * KV_LD + nt * 8 + g]);
                mma_tf32(yacc[nt], a0, a1, a2, a3, b0, b1);
            }
        }

        // ---- write y ----
        #pragma unroll
        for (int nt = 0; nt < 8; nt++) {
            int col = h * HD + nt * 8 + 2 * tg;
            size_t row0 = (size_t)(b * TT + t0 + rb + g);
            *(float2*)(out + row0 * DD + col) = make_float2(yacc[nt][0], yacc[nt][1]);
            *(float2*)(out + (row0 + 8) * DD + col) = make_float2(yacc[nt][2], yacc[nt][3]);
        }
    }
}

// ---------------- launch ----------------
extern "C" void kernel_launch(void* const* d_in, const int* in_sizes, int n_in,
                              void* d_out, int out_size) {
    const float* x     = (const float*)d_in[0];
    const float* xf    = (const float*)d_in[1];
    const float* ln_g  = (const float*)d_in[2];
    const float* ln_b  = (const float*)d_in[3];
    const float* tln_g = (const float*)d_in[4];
    const float* tln_b = (const float*)d_in[5];
    const float* Wq    = (const float*)d_in[6];
    const float* bq    = (const float*)d_in[7];
    const float* Wk    = (const float*)d_in[8];
    const float* bk    = (const float*)d_in[9];
    const float* Wv    = (const float*)d_in[10];
    const float* bv    = (const float*)d_in[11];
    float* out = (float*)d_out;

    void *p_q, *p_k, *p_v, *p_sx, *p_sxf;
    cudaGetSymbolAddress(&p_q,   g_q);
    cudaGetSymbolAddress(&p_k,   g_k);
    cudaGetSymbolAddress(&p_v,   g_v);
    cudaGetSymbolAddress(&p_sx,  g_stats_x);
    cudaGetSymbolAddress(&p_sxf, g_stats_xf);

    cudaFuncSetAttribute(attn_kernel, cudaFuncAttributeMaxDynamicSharedMemorySize,
                         ATTN_SMEM_BYTES);

    // LN stats
    stats_kernel<<<M_X / 8, 256>>>(x,  (float2*)p_sx,  M_X,  DD);
    stats_kernel<<<M_XF / 8, 256>>>(xf, (float2*)p_sxf, M_XF, LL);

    // q = LN(x) @ Wq + bq     (32768 x 512, K=512)
    {
        dim3 grid(DD / GBN, (M_X + GBM - 1) / GBM);   // (4, 256)
        ln_gemm_kernel<<<grid, 256>>>(x, (const float2*)p_sx, ln_g, ln_b,
                                      Wq, bq, (float*)p_q, M_X, DD, DD);
    }
    // k, v = LN(xf) @ {Wk,Wv} + {bk,bv}   (2464 x 512, K=256)
    {
        dim3 grid(DD / GBN, (M_XF + GBM - 1) / GBM);  // (4, 20)
        ln_gemm_kernel<<<grid, 256>>>(xf, (const float2*)p_sxf, tln_g, tln_b,
                                      Wk, bk, (float*)p_k, M_XF, LL, DD);
        ln_gemm_kernel<<<grid, 256>>>(xf, (const float2*)p_sxf, tln_g, tln_b,
                                      Wv, bv, (float*)p_v, M_XF, LL, DD);
    }
    // attention
    {
        dim3 grid(TT / 128, BB);                      // (8, 32)
        attn_kernel<<<grid, 256, ATTN_SMEM_BYTES>>>((const float*)p_q, (const float*)p_k,
                                                    (const float*)p_v, out);
    }
}

// round 3
// speedup vs baseline: 2.0222x; 2.0222x over previous
#include <cuda_runtime.h>
#include <cuda_fp16.h>
#include <cstdint>
#include <cstddef>

// ---------------- problem constants ----------------
#define BB   32
#define TT   1024
#define NN   77
#define DD   512
#define LL   256
#define HH   8
#define HD   64
#define M_X  (BB*TT)          // 32768 rows of x
#define M_XF (BB*NN)          // 2464 rows of xf

// ---------------- scratch (static device, no allocation) ----------------
__device__ __half g_xn [(size_t)M_X * DD];    // 32 MB  LN(x) fp16
__device__ __half g_xfn[(size_t)M_XF * LL];
__device__ __half g_wqT[DD * DD];             // [N][K] fp16 (K-major)
__device__ __half g_wkT[DD * LL];
__device__ __half g_wvT[DD * LL];
__device__ __half g_q[(size_t)M_X * DD];      // 32 MB
__device__ __half g_k[(size_t)M_XF * DD];
__device__ __half g_v[(size_t)M_XF * DD];

// ---------------- primitives ----------------
__device__ __forceinline__ uint32_t smem_u32(const void* p) {
    return (uint32_t)__cvta_generic_to_shared(p);
}
__device__ __forceinline__ void mma_fp16(float* c,
                                         uint32_t a0, uint32_t a1, uint32_t a2, uint32_t a3,
                                         uint32_t b0, uint32_t b1) {
    asm volatile(
        "mma.sync.aligned.m16n8k16.row.col.f32.f16.f16.f32 "
        "{%0,%1,%2,%3}, {%4,%5,%6,%7}, {%8,%9}, {%0,%1,%2,%3};"
        : "+f"(c[0]), "+f"(c[1]), "+f"(c[2]), "+f"(c[3])
        : "r"(a0), "r"(a1), "r"(a2), "r"(a3), "r"(b0), "r"(b1));
}
__device__ __forceinline__ void ldm4(uint32_t* r, uint32_t addr) {
    asm volatile("ldmatrix.sync.aligned.m8n8.x4.shared.b16 {%0,%1,%2,%3}, [%4];"
                 : "=r"(r[0]), "=r"(r[1]), "=r"(r[2]), "=r"(r[3]) : "r"(addr));
}
__device__ __forceinline__ void cp_async16(uint32_t dst, const void* src, int src_bytes) {
    asm volatile("cp.async.cg.shared.global [%0], [%1], 16, %2;"
                 :: "r"(dst), "l"(src), "r"(src_bytes) : "memory");
}

// ---------------- K1: fused LayerNorm (stats + apply), fp16 output ----------------
__global__ __launch_bounds__(256) void ln_apply(const float* __restrict__ X,
    const float* __restrict__ gamma, const float* __restrict__ beta,
    __half* __restrict__ Y, int K)
{
    int row  = blockIdx.x * 8 + (threadIdx.x >> 5);
    int lane = threadIdx.x & 31;
    const float4* p = (const float4*)(X + (size_t)row * K);
    const int cnt = K >> 7;                    // 4 for K=512, 2 for K=256
    float4 v[4];
    float s = 0.f, sq = 0.f;
    #pragma unroll
    for (int j = 0; j < 4; j++) if (j < cnt) {
        v[j] = p[lane + 32 * j];
        s  += v[j].x + v[j].y + v[j].z + v[j].w;
        sq += v[j].x*v[j].x + v[j].y*v[j].y + v[j].z*v[j].z + v[j].w*v[j].w;
    }
    #pragma unroll
    for (int off = 16; off > 0; off >>= 1) {
        s  += __shfl_xor_sync(0xffffffffu, s,  off);
        sq += __shfl_xor_sync(0xffffffffu, sq, off);
    }
    float mean = s / (float)K;
    float var  = fmaxf(sq / (float)K - mean * mean, 0.f);
    float rstd = rsqrtf(var + 1e-5f);
    uint2* o = (uint2*)(Y + (size_t)row * K);
    #pragma unroll
    for (int j = 0; j < 4; j++) if (j < cnt) {
        int idx = lane + 32 * j;
        float4 g4 = ((const float4*)gamma)[idx];
        float4 b4 = ((const float4*)beta)[idx];
        __half2 h01 = __floats2half2_rn((v[j].x - mean) * rstd * g4.x + b4.x,
                                        (v[j].y - mean) * rstd * g4.y + b4.y);
        __half2 h23 = __floats2half2_rn((v[j].z - mean) * rstd * g4.z + b4.z,
                                        (v[j].w - mean) * rstd * g4.w + b4.w);
        uint2 u;
        u.x = *(uint32_t*)&h01;
        u.y = *(uint32_t*)&h23;
        o[idx] = u;
    }
}

// ---------------- K2: weight transpose + fp16 convert : W[K][N] -> WT[N][K] ----------------
__global__ void wconv(const float* __restrict__ W, __half* __restrict__ WT, int K, int N)
{
    __shared__ float t[32][33];
    int nb = blockIdx.x * 32, kb = blockIdx.y * 32;
    int tx = threadIdx.x, ty = threadIdx.y;          // block (32,8)
    for (int i = ty; i < 32; i += 8)
        t[i][tx] = W[(size_t)(kb + i) * N + nb + tx];
    __syncthreads();
    for (int i = ty; i < 32; i += 8)
        WT[(size_t)(nb + i) * K + kb + tx] = __float2half_rn(t[tx][i]);
}

// ---------------- K3: fp16 tensor GEMM  C[M,512] = A[M,K] @ BT[512,K]^T + bias ----------------
// BM=128, BN=128, BK=32 halves, 4-stage cp.async, 8 warps (4m x 2n), warp tile 32x64.
#define GBM 128
#define GBN 128
#define GBK 32
#define LDA 40                     // halves; 80B row stride -> conflict-free ldmatrix
#define TILE_A_BYTES (GBM * LDA * 2)   // 10240
#define STG_BYTES (2 * TILE_A_BYTES)   // A + B per stage = 20480
#define GEMM_SMEM_BYTES (4 * STG_BYTES)  // 81920

__global__ __launch_bounds__(256) void hgemm(const __half* __restrict__ A,
    const __half* __restrict__ BT, const float* __restrict__ bias,
    __half* __restrict__ C, int M, int K)
{
    extern __shared__ char smraw[];
    const uint32_t sb = smem_u32(smraw);
    const int tid  = threadIdx.x;
    const int wid  = tid >> 5;
    const int lane = tid & 31;
    const int m0 = blockIdx.y * GBM;
    const int n0 = blockIdx.x * GBN;
    const int KT = K / GBK;

    const int wm = wid & 3;            // m 0..3 -> rows wm*32
    const int wn = wid >> 2;           // n 0..1 -> cols wn*64
    const int g  = lane >> 2;
    const int tg = lane & 3;
    const int blk  = lane >> 3;        // ldmatrix block id
    const int rin  = lane & 7;         // row within block

    float acc[2][8][4];
    #pragma unroll
    for (int mt = 0; mt < 2; mt++)
        #pragma unroll
        for (int nt = 0; nt < 8; nt++)
            #pragma unroll
            for (int j = 0; j < 4; j++) acc[mt][nt][j] = 0.f;

    auto load_tile = [&](int st, int kt) {
        uint32_t base = sb + st * STG_BYTES;
        #pragma unroll
        for (int i = 0; i < 2; i++) {
            int id = tid + i * 256;        // 0..511
            int r = id >> 2, c = id & 3;   // row, 16B chunk
            int m = m0 + r;
            const __half* src = A + (size_t)((m < M) ? m : (M - 1)) * K + kt * GBK + c * 8;
            cp_async16(base + r * 80 + c * 16, src, (m < M) ? 16 : 0);
        }
        #pragma unroll
        for (int i = 0; i < 2; i++) {
            int id = tid + i * 256;
            int r = id >> 2, c = id & 3;
            const __half* src = BT + (size_t)(n0 + r) * K + kt * GBK + c * 8;
            cp_async16(base + TILE_A_BYTES + r * 80 + c * 16, src, 16);
        }
        asm volatile("cp.async.commit_group;" ::: "memory");
    };

    // prologue: 3 tiles in flight
    #pragma unroll
    for (int p = 0; p < 3; p++) if (p < KT) load_tile(p, p);

    for (int kt = 0; kt < KT; kt++) {
        asm volatile("cp.async.wait_group 2;" ::: "memory");
        __syncthreads();
        const uint32_t aB = sb + (kt & 3) * STG_BYTES;
        const uint32_t bB = aB + TILE_A_BYTES;

        #pragma unroll
        for (int ks = 0; ks < 2; ks++) {
            const int k0 = ks * 16;
            uint32_t af[2][4];
            #pragma unroll
            for (int mt = 0; mt < 2; mt++) {
                int r = wm * 32 + mt * 16 + ((blk & 1) << 3) + rin;
                int c = k0 + ((blk >> 1) << 3);
                ldm4(af[mt], aB + r * 80 + c * 2);
            }
            #pragma unroll
            for (int np = 0; np < 4; np++) {
                uint32_t bf[4];
                int nr = wn * 64 + np * 16 + ((blk >> 1) << 3) + rin;
                int c  = k0 + ((blk & 1) << 3);
                ldm4(bf, bB + nr * 80 + c * 2);
                mma_fp16(acc[0][np*2  ], af[0][0], af[0][1], af[0][2], af[0][3], bf[0], bf[1]);
                mma_fp16(acc[0][np*2+1], af[0][0], af[0][1], af[0][2], af[0][3], bf[2], bf[3]);
                mma_fp16(acc[1][np*2  ], af[1][0], af[1][1], af[1][2], af[1][3], bf[0], bf[1]);
                mma_fp16(acc[1][np*2+1], af[1][0], af[1][1], af[1][2], af[1][3], bf[2], bf[3]);
            }
        }
        if (kt + 3 < KT) load_tile((kt + 3) & 3, kt + 3);
    }

    // epilogue: + bias, fp16 store
    #pragma unroll
    for (int mt = 0; mt < 2; mt++) {
        int r0 = m0 + wm * 32 + mt * 16 + g;
        #pragma unroll
        for (int nt = 0; nt < 8; nt++) {
            int col = n0 + wn * 64 + nt * 8 + 2 * tg;
            float b0 = bias[col], b1 = bias[col + 1];
            if (r0 < M) {
                __half2 h = __floats2half2_rn(acc[mt][nt][0] + b0, acc[mt][nt][1] + b1);
                *(uint32_t*)(C + (size_t)r0 * DD + col) = *(uint32_t*)&h;
            }
            if (r0 + 8 < M) {
                __half2 h = __floats2half2_rn(acc[mt][nt][2] + b0, acc[mt][nt][3] + b1);
                *(uint32_t*)(C + (size_t)(r0 + 8) * DD + col) = *(uint32_t*)&h;
            }
        }
    }
}

// ---------------- K4: fused attention (fp16 mma) ----------------
// grid (8 t-tiles, 32 b), 256 thr (8 warps x 16 rows). Per head:
// stage q[128][64], k[80][64] (zero-pad), v as [64][80] (d-major); S=QK^T; softmax; P@V.
#define LDQ 72     // halves
#define LDK 72
#define LDV 88
#define LDP 88

__global__ __launch_bounds__(256) void attn_kernel(
    const __half* __restrict__ q, const __half* __restrict__ k,
    const __half* __restrict__ v, float* __restrict__ out)
{
    __shared__ __align__(16) __half s_qp[128 * LDP];   // q (LDQ rows) aliased under p (LDP)
    __shared__ __align__(16) __half s_k [80 * LDK];
    __shared__ __align__(16) __half s_v [64 * LDV];

    const int b  = blockIdx.y;
    const int t0 = blockIdx.x * 128;
    const int tid  = threadIdx.x;
    const int wid  = tid >> 5;
    const int lane = tid & 31;
    const int g  = lane >> 2;
    const int tg = lane & 3;
    const int rb = wid * 16;
    const float scale = 0.125f;

    for (int h = 0; h < HH; h++) {
        __syncthreads();   // previous head fully consumed

        // stage q: 128 rows x 8 chunks(16B)
        #pragma unroll
        for (int i = 0; i < 4; i++) {
            int s = tid + i * 256;
            int r = s >> 3, c = s & 7;
            uint4 u = *(const uint4*)(q + (size_t)(b * TT + t0 + r) * DD + h * HD + c * 8);
            *(uint4*)(s_qp + r * LDQ + c * 8) = u;
        }
        // stage k: 80 rows x 8 chunks, zero rows >= 77
        for (int s = tid; s < 80 * 8; s += 256) {
            int n = s >> 3, c = s & 7;
            uint4 u = make_uint4(0u, 0u, 0u, 0u);
            if (n < NN)
                u = *(const uint4*)(k + (size_t)(b * NN + n) * DD + h * HD + c * 8);
            *(uint4*)(s_k + n * LDK + c * 8) = u;
        }
        // stage v transposed: v_s[d][token]
        for (int s = tid; s < 80 * 8; s += 256) {
            int n = s >> 3, c = s & 7;
            uint4 u = make_uint4(0u, 0u, 0u, 0u);
            if (n < NN)
                u = *(const uint4*)(v + (size_t)(b * NN + n) * DD + h * HD + c * 8);
            __half hv[8];
            *(uint4*)hv = u;
            #pragma unroll
            for (int j = 0; j < 8; j++)
                s_v[(c * 8 + j) * LDV + n] = hv[j];
        }
        __syncthreads();

        // ---- S = q @ k^T : 16 x 80 per warp, K=64 (4 k16 steps) ----
        float sacc[10][4];
        #pragma unroll
        for (int nt = 0; nt < 10; nt++)
            #pragma unroll
            for (int j = 0; j < 4; j++) sacc[nt][j] = 0.f;

        #pragma unroll
        for (int ks = 0; ks < 4; ks++) {
            const int k0 = ks * 16;
            uint32_t a0 = *(const uint32_t*)(s_qp + (rb + g    ) * LDQ + k0 + 2 * tg);
            uint32_t a1 = *(const uint32_t*)(s_qp + (rb + 8 + g) * LDQ + k0 + 2 * tg);
            uint32_t a2 = *(const uint32_t*)(s_qp + (rb + g    ) * LDQ + k0 + 8 + 2 * tg);
            uint32_t a3 = *(const uint32_t*)(s_qp + (rb + 8 + g) * LDQ + k0 + 8 + 2 * tg);
            #pragma unroll
            for (int nt = 0; nt < 10; nt++) {
                uint32_t b0 = *(const uint32_t*)(s_k + (nt * 8 + g) * LDK + k0 + 2 * tg);
                uint32_t b1 = *(const uint32_t*)(s_k + (nt * 8 + g) * LDK + k0 + 8 + 2 * tg);
                mma_fp16(sacc[nt], a0, a1, a2, a3, b0, b1);
            }
        }

        // ---- masked softmax over tokens ----
        float mx0 = -1e30f, mx1 = -1e30f;
        #pragma unroll
        for (int nt = 0; nt < 10; nt++) {
            int c0 = nt * 8 + 2 * tg;
            sacc[nt][0] = (c0     < NN) ? sacc[nt][0] * scale : -1e30f;
            sacc[nt][1] = (c0 + 1 < NN) ? sacc[nt][1] * scale : -1e30f;
            sacc[nt][2] = (c0     < NN) ? sacc[nt][2] * scale : -1e30f;
            sacc[nt][3] = (c0 + 1 < NN) ? sacc[nt][3] * scale : -1e30f;
            mx0 = fmaxf(mx0, fmaxf(sacc[nt][0], sacc[nt][1]));
            mx1 = fmaxf(mx1, fmaxf(sacc[nt][2], sacc[nt][3]));
        }
        mx0 = fmaxf(mx0, __shfl_xor_sync(0xffffffffu, mx0, 1));
        mx0 = fmaxf(mx0, __shfl_xor_sync(0xffffffffu, mx0, 2));
        mx1 = fmaxf(mx1, __shfl_xor_sync(0xffffffffu, mx1, 1));
        mx1 = fmaxf(mx1, __shfl_xor_sync(0xffffffffu, mx1, 2));

        float s0 = 0.f, s1 = 0.f;
        #pragma unroll
        for (int nt = 0; nt < 10; nt++) {
            sacc[nt][0] = __expf(sacc[nt][0] - mx0);
            sacc[nt][1] = __expf(sacc[nt][1] - mx0);
            sacc[nt][2] = __expf(sacc[nt][2] - mx1);
            sacc[nt][3] = __expf(sacc[nt][3] - mx1);
            s0 += sacc[nt][0] + sacc[nt][1];
            s1 += sacc[nt][2] + sacc[nt][3];
        }
        s0 += __shfl_xor_sync(0xffffffffu, s0, 1);
        s0 += __shfl_xor_sync(0xffffffffu, s0, 2);
        s1 += __shfl_xor_sync(0xffffffffu, s1, 1);
        s1 += __shfl_xor_sync(0xffffffffu, s1, 2);
        const float inv0 = 1.0f / s0;
        const float inv1 = 1.0f / s1;

        __syncthreads();   // everyone done reading q region before P overwrites it

        // ---- store P (fp16) ----
        #pragma unroll
        for (int nt = 0; nt < 10; nt++) {
            int c0 = nt * 8 + 2 * tg;
            __half2 p01 = __floats2half2_rn(sacc[nt][0] * inv0, sacc[nt][1] * inv0);
            __half2 p23 = __floats2half2_rn(sacc[nt][2] * inv1, sacc[nt][3] * inv1);
            *(uint32_t*)(s_qp + (rb + g    ) * LDP + c0) = *(uint32_t*)&p01;
            *(uint32_t*)(s_qp + (rb + 8 + g) * LDP + c0) = *(uint32_t*)&p23;
        }
        __syncwarp();

        // ---- Y = P @ V : 16 x 64, K=80 (5 k16 steps) ----
        float yacc[8][4];
        #pragma unroll
        for (int nt = 0; nt < 8; nt++)
            #pragma unroll
            for (int j = 0; j < 4; j++) yacc[nt][j] = 0.f;

        #pragma unroll
        for (int ks = 0; ks < 5; ks++) {
            const int k0 = ks * 16;
            uint32_t a0 = *(const uint32_t*)(s_qp + (rb + g    ) * LDP + k0 + 2 * tg);
            uint32_t a1 = *(const uint32_t*)(s_qp + (rb + 8 + g) * LDP + k0 + 2 * tg);
            uint32_t a2 = *(const uint32_t*)(s_qp + (rb + g    ) * LDP + k0 + 8 + 2 * tg);
            uint32_t a3 = *(const uint32_t*)(s_qp + (rb + 8 + g) * LDP + k0 + 8 + 2 * tg);
            #pragma unroll
            for (int nt = 0; nt < 8; nt++) {
                uint32_t b0 = *(const uint32_t*)(s_v + (nt * 8 + g) * LDV + k0 + 2 * tg);
                uint32_t b1 = *(const uint32_t*)(s_v + (nt * 8 + g) * LDV + k0 + 8 + 2 * tg);
                mma_fp16(yacc[nt], a0, a1, a2, a3, b0, b1);
            }
        }

        // ---- write y (fp32) ----
        #pragma unroll
        for (int nt = 0; nt < 8; nt++) {
            int col = h * HD + nt * 8 + 2 * tg;
            size_t row0 = (size_t)(b * TT + t0 + rb + g);
            *(float2*)(out + row0 * DD + col) = make_float2(yacc[nt][0], yacc[nt][1]);
            *(float2*)(out + (row0 + 8) * DD + col) = make_float2(yacc[nt][2], yacc[nt][3]);
        }
    }
}

// ---------------- launch ----------------
extern "C" void kernel_launch(void* const* d_in, const int* in_sizes, int n_in,
                              void* d_out, int out_size) {
    const float* x     = (const float*)d_in[0];
    const float* xf    = (const float*)d_in[1];
    const float* ln_g  = (const float*)d_in[2];
    const float* ln_b  = (const float*)d_in[3];
    const float* tln_g = (const float*)d_in[4];
    const float* tln_b = (const float*)d_in[5];
    const float* Wq    = (const float*)d_in[6];
    const float* bq    = (const float*)d_in[7];
    const float* Wk    = (const float*)d_in[8];
    const float* bk    = (const float*)d_in[9];
    const float* Wv    = (const float*)d_in[10];
    const float* bv    = (const float*)d_in[11];
    float* out = (float*)d_out;

    void *p_xn, *p_xfn, *p_wqT, *p_wkT, *p_wvT, *p_q, *p_k, *p_v;
    cudaGetSymbolAddress(&p_xn,  g_xn);
    cudaGetSymbolAddress(&p_xfn, g_xfn);
    cudaGetSymbolAddress(&p_wqT, g_wqT);
    cudaGetSymbolAddress(&p_wkT, g_wkT);
    cudaGetSymbolAddress(&p_wvT, g_wvT);
    cudaGetSymbolAddress(&p_q,   g_q);
    cudaGetSymbolAddress(&p_k,   g_k);
    cudaGetSymbolAddress(&p_v,   g_v);

    cudaFuncSetAttribute(hgemm, cudaFuncAttributeMaxDynamicSharedMemorySize,
                         GEMM_SMEM_BYTES);

    // LayerNorms (fused stats+apply, fp16 out)
    ln_apply<<<M_X / 8,  256>>>(x,  ln_g,  ln_b,  (__half*)p_xn,  DD);
    ln_apply<<<M_XF / 8, 256>>>(xf, tln_g, tln_b, (__half*)p_xfn, LL);

    // weight transpose + fp16 convert
    {
        dim3 blk(32, 8);
        wconv<<<dim3(DD / 32, DD / 32), blk>>>(Wq, (__half*)p_wqT, DD, DD);
        wconv<<<dim3(DD / 32, LL / 32), blk>>>(Wk, (__half*)p_wkT, LL, DD);
        wconv<<<dim3(DD / 32, LL / 32), blk>>>(Wv, (__half*)p_wvT, LL, DD);
    }

    // q = xn @ Wq + bq    (32768 x 512, K=512)
    hgemm<<<dim3(DD / GBN, M_X / GBM), 256, GEMM_SMEM_BYTES>>>(
        (const __half*)p_xn, (const __half*)p_wqT, bq, (__half*)p_q, M_X, DD);
    // k, v = xfn @ {Wk,Wv}   (2464 x 512, K=256)
    {
        dim3 grid(DD / GBN, (M_XF + GBM - 1) / GBM);   // (4, 20)
        hgemm<<<grid, 256, GEMM_SMEM_BYTES>>>(
            (const __half*)p_xfn, (const __half*)p_wkT, bk, (__half*)p_k, M_XF, LL);
        hgemm<<<grid, 256, GEMM_SMEM_BYTES>>>(
            (const __half*)p_xfn, (const __half*)p_wvT, bv, (__half*)p_v, M_XF, LL);
    }
    // attention
    attn_kernel<<<dim3(TT / 128, BB), 256>>>((const __half*)p_q, (const __half*)p_k,
                                             (const __half*)p_v, out);
}

// round 5
// speedup vs baseline: 2.3052x; 1.1399x over previous
#include <cuda_runtime.h>
#include <cuda_fp16.h>
#include <cstdint>
#include <cstddef>

// ---------------- problem constants ----------------
#define BB   32
#define TT   1024
#define NN   77
#define DD   512
#define LL   256
#define HH   8
#define HD   64
#define M_X  (BB*TT)          // 32768 rows of x
#define M_XF (BB*NN)          // 2464 rows of xf

// ---------------- scratch (static device, no allocation) ----------------
__device__ __half g_xn [(size_t)M_X * DD];    // 32 MB  LN(x) fp16
__device__ __half g_xfn[(size_t)M_XF * LL];
__device__ __half g_wqT[DD * DD];             // [N][K] fp16 (K-major)
__device__ __half g_wkT[DD * LL];
__device__ __half g_wvT[DD * LL];
__device__ __half g_q[(size_t)M_X * DD];      // 32 MB
__device__ __half g_k[(size_t)M_XF * DD];
__device__ __half g_v[(size_t)M_XF * DD];

// ---------------- primitives ----------------
__device__ __forceinline__ uint32_t smem_u32(const void* p) {
    return (uint32_t)__cvta_generic_to_shared(p);
}
__device__ __forceinline__ void mma_fp16(float* c,
                                         uint32_t a0, uint32_t a1, uint32_t a2, uint32_t a3,
                                         uint32_t b0, uint32_t b1) {
    asm volatile(
        "mma.sync.aligned.m16n8k16.row.col.f32.f16.f16.f32 "
        "{%0,%1,%2,%3}, {%4,%5,%6,%7}, {%8,%9}, {%0,%1,%2,%3};"
        : "+f"(c[0]), "+f"(c[1]), "+f"(c[2]), "+f"(c[3])
        : "r"(a0), "r"(a1), "r"(a2), "r"(a3), "r"(b0), "r"(b1));
}
__device__ __forceinline__ void ldm4(uint32_t* r, uint32_t addr) {
    asm volatile("ldmatrix.sync.aligned.m8n8.x4.shared.b16 {%0,%1,%2,%3}, [%4];"
                 : "=r"(r[0]), "=r"(r[1]), "=r"(r[2]), "=r"(r[3]) : "r"(addr));
}
__device__ __forceinline__ void cp_async16(uint32_t dst, const void* src) {
    asm volatile("cp.async.cg.shared.global [%0], [%1], 16;"
                 :: "r"(dst), "l"(src) : "memory");
}

// ---------------- K1: prep = LN(x) + LN(xf) + 3 weight transposes, one launch ----------------
// blocks [0,4096): ln rows of x ; [4096,4404): ln rows of xf ; [4404,4916): wconv 32x32 tiles
#define LN_X_BLOCKS   (M_X / 8)            // 4096
#define LN_XF_BLOCKS  (M_XF / 8)           // 308
#define WCONV_OFF     (LN_X_BLOCKS + LN_XF_BLOCKS)   // 4404
#define PREP_BLOCKS   (WCONV_OFF + 512)    // Wq 256, Wk 128, Wv 128

__global__ __launch_bounds__(256) void prep_kernel(
    const float* __restrict__ x,  const float* __restrict__ xf,
    const float* __restrict__ ln_g,  const float* __restrict__ ln_b,
    const float* __restrict__ tln_g, const float* __restrict__ tln_b,
    const float* __restrict__ Wq, const float* __restrict__ Wk, const float* __restrict__ Wv)
{
    __shared__ float t[32][33];
    const int bid = blockIdx.x;
    const int tid = threadIdx.x;

    if (bid < WCONV_OFF) {
        // ---- LayerNorm path ----
        const float* X;
        const float* gamma;
        const float* beta;
        __half* Y;
        int K, row;
        if (bid < LN_X_BLOCKS) {
            X = x; gamma = ln_g; beta = ln_b; Y = g_xn; K = DD;
            row = bid * 8 + (tid >> 5);
        } else {
            X = xf; gamma = tln_g; beta = tln_b; Y = g_xfn; K = LL;
            row = (bid - LN_X_BLOCKS) * 8 + (tid >> 5);
        }
        int lane = tid & 31;
        const float4* p = (const float4*)(X + (size_t)row * K);
        const int cnt = K >> 7;
        float4 v[4];
        float s = 0.f, sq = 0.f;
        #pragma unroll
        for (int j = 0; j < 4; j++) if (j < cnt) {
            v[j] = p[lane + 32 * j];
            s  += v[j].x + v[j].y + v[j].z + v[j].w;
            sq += v[j].x*v[j].x + v[j].y*v[j].y + v[j].z*v[j].z + v[j].w*v[j].w;
        }
        #pragma unroll
        for (int off = 16; off > 0; off >>= 1) {
            s  += __shfl_xor_sync(0xffffffffu, s,  off);
            sq += __shfl_xor_sync(0xffffffffu, sq, off);
        }
        float mean = s / (float)K;
        float var  = fmaxf(sq / (float)K - mean * mean, 0.f);
        float rstd = rsqrtf(var + 1e-5f);
        uint2* o = (uint2*)(Y + (size_t)row * K);
        #pragma unroll
        for (int j = 0; j < 4; j++) if (j < cnt) {
            int idx = lane + 32 * j;
            float4 g4 = ((const float4*)gamma)[idx];
            float4 b4 = ((const float4*)beta)[idx];
            __half2 h01 = __floats2half2_rn((v[j].x - mean) * rstd * g4.x + b4.x,
                                            (v[j].y - mean) * rstd * g4.y + b4.y);
            __half2 h23 = __floats2half2_rn((v[j].z - mean) * rstd * g4.z + b4.z,
                                            (v[j].w - mean) * rstd * g4.w + b4.w);
            uint2 u;
            u.x = *(uint32_t*)&h01;
            u.y = *(uint32_t*)&h23;
            o[idx] = u;
        }
    } else {
        // ---- weight transpose path: W[K][N] -> WT[N][K] fp16 ----
        int wt = bid - WCONV_OFF;
        const float* W;
        __half* WT;
        int K, nt, kt;
        if (wt < 256)      { W = Wq; WT = g_wqT; K = DD; nt = wt % 16;        kt = wt / 16; }
        else if (wt < 384) { W = Wk; WT = g_wkT; K = LL; nt = (wt-256) % 16;  kt = (wt-256) / 16; }
        else               { W = Wv; WT = g_wvT; K = LL; nt = (wt-384) % 16;  kt = (wt-384) / 16; }
        int nb = nt * 32, kb = kt * 32;
        int tx = tid & 31, ty = tid >> 5;
        for (int i = ty; i < 32; i += 8)
            t[i][tx] = W[(size_t)(kb + i) * DD + nb + tx];
        __syncthreads();
        for (int i = ty; i < 32; i += 8)
            WT[(size_t)(nb + i) * K + kb + tx] = __float2half_rn(t[tx][i]);
    }
}

// ---------------- K2: persistent fp16 tensor GEMM ----------------
// C[M,512] = A[M,K] @ BT[512,K]^T + bias.  Tile 128x128x64, 3 stages, XOR-swizzled
// 32KB stages, 8 warps (4m x 2n), warp tile 32x64. Tile id >= tiles_per_w selects set 1.
#define GBK 64
#define A_BYTES 16384                  // 128 rows x 128B
#define STG_BYTES 32768
#define NSTG 3
#define GEMM_SMEM (NSTG * STG_BYTES)   // 98304

__global__ __launch_bounds__(256, 2) void hgemm(
    const __half* __restrict__ A,
    const __half* __restrict__ BT0, const __half* __restrict__ BT1,
    const float* __restrict__ bias0, const float* __restrict__ bias1,
    __half* __restrict__ C0, __half* __restrict__ C1,
    int M, int K, int KT, int ntiles, int tiles_per_w)
{
    extern __shared__ char smraw[];
    const uint32_t sb = smem_u32(smraw);
    const int tid  = threadIdx.x;
    const int wid  = tid >> 5;
    const int lane = tid & 31;
    const int wm = wid & 3;
    const int wn = wid >> 2;
    const int g  = lane >> 2;
    const int tg = lane & 3;
    const int blk = lane >> 3;
    const int rin = lane & 7;
    const int G = (int)gridDim.x;

    // loader state
    int t_l = blockIdx.x, kt_l = 0;

    auto load_step = [&](int st) {
        if (t_l < ntiles) {
            int w = (t_l >= tiles_per_w) ? 1 : 0;
            int r = t_l - (w ? tiles_per_w : 0);
            int m0 = (r >> 2) * 128;
            int n0 = (r & 3) * 128;
            const __half* Bt = w ? BT1 : BT0;
            uint32_t base = sb + st * STG_BYTES;
            #pragma unroll
            for (int i = 0; i < 4; i++) {
                int id = tid + i * 256;
                int row = id >> 3, c = id & 7;
                int m = m0 + row;
                if (m >= M) m = M - 1;
                cp_async16(base + row * 128 + ((c ^ (row & 7)) << 4),
                           A + (size_t)m * K + kt_l * GBK + c * 8);
            }
            #pragma unroll
            for (int i = 0; i < 4; i++) {
                int id = tid + i * 256;
                int row = id >> 3, c = id & 7;
                cp_async16(base + A_BYTES + row * 128 + ((c ^ (row & 7)) << 4),
                           Bt + (size_t)(n0 + row) * K + kt_l * GBK + c * 8);
            }
        }
        asm volatile("cp.async.commit_group;" ::: "memory");
        if (++kt_l == KT) { kt_l = 0; t_l += G; }
    };

    float acc[2][8][4];
    #pragma unroll
    for (int mt = 0; mt < 2; mt++)
        #pragma unroll
        for (int nt = 0; nt < 8; nt++)
            #pragma unroll
            for (int j = 0; j < 4; j++) acc[mt][nt][j] = 0.f;

    // prologue: 2 stages in flight
    load_step(0);
    load_step(1);

    int stage = 0;
    int t_c = blockIdx.x, kt_c = 0;

    while (t_c < ntiles) {
        asm volatile("cp.async.wait_group 1;" ::: "memory");
        __syncthreads();
        const uint32_t aB = sb + stage * STG_BYTES;
        const uint32_t bB = aB + A_BYTES;

        #pragma unroll
        for (int ks = 0; ks < 4; ks++) {
            uint32_t af[2][4];
            #pragma unroll
            for (int mt = 0; mt < 2; mt++) {
                int row = wm * 32 + mt * 16 + ((blk & 1) << 3) + rin;
                int ch  = 2 * ks + (blk >> 1);
                ldm4(af[mt], aB + row * 128 + ((ch ^ (row & 7)) << 4));
            }
            #pragma unroll
            for (int np = 0; np < 4; np++) {
                uint32_t bf[4];
                int nr = wn * 64 + np * 16 + ((blk >> 1) << 3) + rin;
                int ch = 2 * ks + (blk & 1);
                ldm4(bf, bB + nr * 128 + ((ch ^ (nr & 7)) << 4));
                mma_fp16(acc[0][np*2  ], af[0][0], af[0][1], af[0][2], af[0][3], bf[0], bf[1]);
                mma_fp16(acc[0][np*2+1], af[0][0], af[0][1], af[0][2], af[0][3], bf[2], bf[3]);
                mma_fp16(acc[1][np*2  ], af[1][0], af[1][1], af[1][2], af[1][3], bf[0], bf[1]);
                mma_fp16(acc[1][np*2+1], af[1][0], af[1][1], af[1][2], af[1][3], bf[2], bf[3]);
            }
        }

        // prefetch stage (current + 2) mod 3
        int nst = stage + 2;
        if (nst >= NSTG) nst -= NSTG;
        load_step(nst);

        if (++kt_c == KT) {
            // epilogue for tile t_c (no smem involved; pipeline keeps running)
            int w = (t_c >= tiles_per_w) ? 1 : 0;
            int r = t_c - (w ? tiles_per_w : 0);
            int m0 = (r >> 2) * 128;
            int n0 = (r & 3) * 128;
            const float* bias = w ? bias1 : bias0;
            __half* C = w ? C1 : C0;
            #pragma unroll
            for (int mt = 0; mt < 2; mt++) {
                int r0 = m0 + wm * 32 + mt * 16 + g;
                #pragma unroll
                for (int nt = 0; nt < 8; nt++) {
                    int col = n0 + wn * 64 + nt * 8 + 2 * tg;
                    float b0 = bias[col], b1 = bias[col + 1];
                    if (r0 < M) {
                        __half2 h = __floats2half2_rn(acc[mt][nt][0] + b0, acc[mt][nt][1] + b1);
                        *(uint32_t*)(C + (size_t)r0 * DD + col) = *(uint32_t*)&h;
                    }
                    if (r0 + 8 < M) {
                        __half2 h = __floats2half2_rn(acc[mt][nt][2] + b0, acc[mt][nt][3] + b1);
                        *(uint32_t*)(C + (size_t)(r0 + 8) * DD + col) = *(uint32_t*)&h;
                    }
                    acc[mt][nt][0] = 0.f; acc[mt][nt][1] = 0.f;
                    acc[mt][nt][2] = 0.f; acc[mt][nt][3] = 0.f;
                }
            }
            kt_c = 0;
            t_c += G;
        }
        if (++stage == NSTG) stage = 0;
    }
}

// ---------------- K3: fused attention (fp16 mma) ----------------
#define LDQ 72
#define LDK 72
#define LDV 88
#define LDP 88

__global__ __launch_bounds__(256) void attn_kernel(
    const __half* __restrict__ q, const __half* __restrict__ k,
    const __half* __restrict__ v, float* __restrict__ out)
{
    __shared__ __align__(16) __half s_qp[128 * LDP];
    __shared__ __align__(16) __half s_k [80 * LDK];
    __shared__ __align__(16) __half s_v [64 * LDV];

    const int b  = blockIdx.y;
    const int t0 = blockIdx.x * 128;
    const int tid  = threadIdx.x;
    const int wid  = tid >> 5;
    const int lane = tid & 31;
    const int g  = lane >> 2;
    const int tg = lane & 3;
    const int rb = wid * 16;
    const float scale = 0.125f;

    for (int h = 0; h < HH; h++) {
        __syncthreads();

        #pragma unroll
        for (int i = 0; i < 4; i++) {
            int s = tid + i * 256;
            int r = s >> 3, c = s & 7;
            uint4 u = *(const uint4*)(q + (size_t)(b * TT + t0 + r) * DD + h * HD + c * 8);
            *(uint4*)(s_qp + r * LDQ + c * 8) = u;
        }
        for (int s = tid; s < 80 * 8; s += 256) {
            int n = s >> 3, c = s & 7;
            uint4 u = make_uint4(0u, 0u, 0u, 0u);
            if (n < NN)
                u = *(const uint4*)(k + (size_t)(b * NN + n) * DD + h * HD + c * 8);
            *(uint4*)(s_k + n * LDK + c * 8) = u;
        }
        for (int s = tid; s < 80 * 8; s += 256) {
            int n = s >> 3, c = s & 7;
            uint4 u = make_uint4(0u, 0u, 0u, 0u);
            if (n < NN)
                u = *(const uint4*)(v + (size_t)(b * NN + n) * DD + h * HD + c * 8);
            __half hv[8];
            *(uint4*)hv = u;
            #pragma unroll
            for (int j = 0; j < 8; j++)
                s_v[(c * 8 + j) * LDV + n] = hv[j];
        }
        __syncthreads();

        float sacc[10][4];
        #pragma unroll
        for (int nt = 0; nt < 10; nt++)
            #pragma unroll
            for (int j = 0; j < 4; j++) sacc[nt][j] = 0.f;

        #pragma unroll
        for (int ks = 0; ks < 4; ks++) {
            const int k0 = ks * 16;
            uint32_t a0 = *(const uint32_t*)(s_qp + (rb + g    ) * LDQ + k0 + 2 * tg);
            uint32_t a1 = *(const uint32_t*)(s_qp + (rb + 8 + g) * LDQ + k0 + 2 * tg);
            uint32_t a2 = *(const uint32_t*)(s_qp + (rb + g    ) * LDQ + k0 + 8 + 2 * tg);
            uint32_t a3 = *(const uint32_t*)(s_qp + (rb + 8 + g) * LDQ + k0 + 8 + 2 * tg);
            #pragma unroll
            for (int nt = 0; nt < 10; nt++) {
                uint32_t b0 = *(const uint32_t*)(s_k + (nt * 8 + g) * LDK + k0 + 2 * tg);
                uint32_t b1 = *(const uint32_t*)(s_k + (nt * 8 + g) * LDK + k0 + 8 + 2 * tg);
                mma_fp16(sacc[nt], a0, a1, a2, a3, b0, b1);
            }
        }

        float mx0 = -1e30f, mx1 = -1e30f;
        #pragma unroll
        for (int nt = 0; nt < 10; nt++) {
            int c0 = nt * 8 + 2 * tg;
            sacc[nt][0] = (c0     < NN) ? sacc[nt][0] * scale : -1e30f;
            sacc[nt][1] = (c0 + 1 < NN) ? sacc[nt][1] * scale : -1e30f;
            sacc[nt][2] = (c0     < NN) ? sacc[nt][2] * scale : -1e30f;
            sacc[nt][3] = (c0 + 1 < NN) ? sacc[nt][3] * scale : -1e30f;
            mx0 = fmaxf(mx0, fmaxf(sacc[nt][0], sacc[nt][1]));
            mx1 = fmaxf(mx1, fmaxf(sacc[nt][2], sacc[nt][3]));
        }
        mx0 = fmaxf(mx0, __shfl_xor_sync(0xffffffffu, mx0, 1));
        mx0 = fmaxf(mx0, __shfl_xor_sync(0xffffffffu, mx0, 2));
        mx1 = fmaxf(mx1, __shfl_xor_sync(0xffffffffu, mx1, 1));
        mx1 = fmaxf(mx1, __shfl_xor_sync(0xffffffffu, mx1, 2));

        float s0 = 0.f, s1 = 0.f;
        #pragma unroll
        for (int nt = 0; nt < 10; nt++) {
            sacc[nt][0] = __expf(sacc[nt][0] - mx0);
            sacc[nt][1] = __expf(sacc[nt][1] - mx0);
            sacc[nt][2] = __expf(sacc[nt][2] - mx1);
            sacc[nt][3] = __expf(sacc[nt][3] - mx1);
            s0 += sacc[nt][0] + sacc[nt][1];
            s1 += sacc[nt][2] + sacc[nt][3];
        }
        s0 += __shfl_xor_sync(0xffffffffu, s0, 1);
        s0 += __shfl_xor_sync(0xffffffffu, s0, 2);
        s1 += __shfl_xor_sync(0xffffffffu, s1, 1);
        s1 += __shfl_xor_sync(0xffffffffu, s1, 2);
        const float inv0 = 1.0f / s0;
        const float inv1 = 1.0f / s1;

        __syncthreads();

        #pragma unroll
        for (int nt = 0; nt < 10; nt++) {
            int c0 = nt * 8 + 2 * tg;
            __half2 p01 = __floats2half2_rn(sacc[nt][0] * inv0, sacc[nt][1] * inv0);
            __half2 p23 = __floats2half2_rn(sacc[nt][2] * inv1, sacc[nt][3] * inv1);
            *(uint32_t*)(s_qp + (rb + g    ) * LDP + c0) = *(uint32_t*)&p01;
            *(uint32_t*)(s_qp + (rb + 8 + g) * LDP + c0) = *(uint32_t*)&p23;
        }
        __syncwarp();

        float yacc[8][4];
        #pragma unroll
        for (int nt = 0; nt < 8; nt++)
            #pragma unroll
            for (int j = 0; j < 4; j++) yacc[nt][j] = 0.f;

        #pragma unroll
        for (int ks = 0; ks < 5; ks++) {
            const int k0 = ks * 16;
            uint32_t a0 = *(const uint32_t*)(s_qp + (rb + g    ) * LDP + k0 + 2 * tg);
            uint32_t a1 = *(const uint32_t*)(s_qp + (rb + 8 + g) * LDP + k0 + 2 * tg);
            uint32_t a2 = *(const uint32_t*)(s_qp + (rb + g    ) * LDP + k0 + 8 + 2 * tg);
            uint32_t a3 = *(const uint32_t*)(s_qp + (rb + 8 + g) * LDP + k0 + 8 + 2 * tg);
            #pragma unroll
            for (int nt = 0; nt < 8; nt++) {
                uint32_t b0 = *(const uint32_t*)(s_v + (nt * 8 + g) * LDV + k0 + 2 * tg);
                uint32_t b1 = *(const uint32_t*)(s_v + (nt * 8 + g) * LDV + k0 + 8 + 2 * tg);
                mma_fp16(yacc[nt], a0, a1, a2, a3, b0, b1);
            }
        }

        #pragma unroll
        for (int nt = 0; nt < 8; nt++) {
            int col = h * HD + nt * 8 + 2 * tg;
            size_t row0 = (size_t)(b * TT + t0 + rb + g);
            *(float2*)(out + row0 * DD + col) = make_float2(yacc[nt][0], yacc[nt][1]);
            *(float2*)(out + (row0 + 8) * DD + col) = make_float2(yacc[nt][2], yacc[nt][3]);
        }
    }
}

// ---------------- launch ----------------
extern "C" void kernel_launch(void* const* d_in, const int* in_sizes, int n_in,
                              void* d_out, int out_size) {
    const float* x     = (const float*)d_in[0];
    const float* xf    = (const float*)d_in[1];
    const float* ln_g  = (const float*)d_in[2];
    const float* ln_b  = (const float*)d_in[3];
    const float* tln_g = (const float*)d_in[4];
    const float* tln_b = (const float*)d_in[5];
    const float* Wq    = (const float*)d_in[6];
    const float* bq    = (const float*)d_in[7];
    const float* Wk    = (const float*)d_in[8];
    const float* bk    = (const float*)d_in[9];
    const float* Wv    = (const float*)d_in[10];
    const float* bv    = (const float*)d_in[11];
    float* out = (float*)d_out;

    void *p_xn, *p_xfn, *p_wqT, *p_wkT, *p_wvT, *p_q, *p_k, *p_v;
    cudaGetSymbolAddress(&p_xn,  g_xn);
    cudaGetSymbolAddress(&p_xfn, g_xfn);
    cudaGetSymbolAddress(&p_wqT, g_wqT);
    cudaGetSymbolAddress(&p_wkT, g_wkT);
    cudaGetSymbolAddress(&p_wvT, g_wvT);
    cudaGetSymbolAddress(&p_q,   g_q);
    cudaGetSymbolAddress(&p_k,   g_k);
    cudaGetSymbolAddress(&p_v,   g_v);

    cudaFuncSetAttribute(hgemm, cudaFuncAttributeMaxDynamicSharedMemorySize, GEMM_SMEM);

    // 1) prep: both LayerNorms + all three weight transposes
    prep_kernel<<<PREP_BLOCKS, 256>>>(x, xf, ln_g, ln_b, tln_g, tln_b, Wq, Wk, Wv);

    // 2) q = xn @ Wq + bq : 1024 tiles (256 m-blocks x 4 n-blocks), persistent over 296 CTAs
    hgemm<<<296, 256, GEMM_SMEM>>>(
        (const __half*)p_xn, (const __half*)p_wqT, (const __half*)p_wqT,
        bq, bq, (__half*)p_q, (__half*)p_q,
        M_X, DD, DD / GBK, 1024, 1024);

    // 3) k,v = xfn @ {Wk,Wv} : 80 tiles each (20 m-blocks x 4 n-blocks), one launch
    hgemm<<<160, 256, GEMM_SMEM>>>(
        (const __half*)p_xfn, (const __half*)p_wkT, (const __half*)p_wvT,
        bk, bv, (__half*)p_k, (__half*)p_v,
        M_XF, LL, LL / GBK, 160, 80);

    // 4) attention
    attn_kernel<<<dim3(TT / 128, BB), 256>>>((const __half*)p_q, (const __half*)p_k,
                                             (const __half*)p_v, out);
}

// round 7
// speedup vs baseline: 2.7183x; 1.1792x over previous
#include <cuda_runtime.h>
#include <cuda_fp16.h>
#include <cstdint>
#include <cstddef>

// ---------------- problem constants ----------------
#define BB   32
#define TT   1024
#define NN   77
#define DD   512
#define LL   256
#define HH   8
#define HD   64
#define M_X  (BB*TT)          // 32768 rows of x
#define M_XF (BB*NN)          // 2464 rows of xf

// ---------------- scratch (static device, no allocation) ----------------
__device__ __half g_xn [(size_t)M_X * DD];    // 32 MB  LN(x) fp16
__device__ __half g_xfn[(size_t)M_XF * LL];
__device__ __half g_wqT[DD * DD];             // [N][K] fp16 (K-major)
__device__ __half g_wkT[DD * LL];
__device__ __half g_wvT[DD * LL];
__device__ __half g_q[(size_t)M_X * DD];      // 32 MB
__device__ __half g_k[(size_t)M_XF * DD];
__device__ __half g_v[(size_t)M_XF * DD];

// ---------------- primitives ----------------
__device__ __forceinline__ uint32_t smem_u32(const void* p) {
    return (uint32_t)__cvta_generic_to_shared(p);
}
__device__ __forceinline__ void mma_fp16(float* c,
                                         uint32_t a0, uint32_t a1, uint32_t a2, uint32_t a3,
                                         uint32_t b0, uint32_t b1) {
    asm volatile(
        "mma.sync.aligned.m16n8k16.row.col.f32.f16.f16.f32 "
        "{%0,%1,%2,%3}, {%4,%5,%6,%7}, {%8,%9}, {%0,%1,%2,%3};"
        : "+f"(c[0]), "+f"(c[1]), "+f"(c[2]), "+f"(c[3])
        : "r"(a0), "r"(a1), "r"(a2), "r"(a3), "r"(b0), "r"(b1));
}
__device__ __forceinline__ void ldm4(uint32_t* r, uint32_t addr) {
    asm volatile("ldmatrix.sync.aligned.m8n8.x4.shared.b16 {%0,%1,%2,%3}, [%4];"
                 : "=r"(r[0]), "=r"(r[1]), "=r"(r[2]), "=r"(r[3]) : "r"(addr));
}
__device__ __forceinline__ void ldm4t(uint32_t* r, uint32_t addr) {
    asm volatile("ldmatrix.sync.aligned.m8n8.x4.trans.shared.b16 {%0,%1,%2,%3}, [%4];"
                 : "=r"(r[0]), "=r"(r[1]), "=r"(r[2]), "=r"(r[3]) : "r"(addr));
}
__device__ __forceinline__ void cp_async16(uint32_t dst, const void* src) {
    asm volatile("cp.async.cg.shared.global [%0], [%1], 16;"
                 :: "r"(dst), "l"(src) : "memory");
}

// ---------------- K1: prep = LN(x) + LN(xf) + 3 weight transposes, one launch ----------------
#define LN_X_BLOCKS   (M_X / 8)            // 4096
#define LN_XF_BLOCKS  (M_XF / 8)           // 308
#define WCONV_OFF     (LN_X_BLOCKS + LN_XF_BLOCKS)   // 4404
#define PREP_BLOCKS   (WCONV_OFF + 512)    // Wq 256, Wk 128, Wv 128

__global__ __launch_bounds__(256) void prep_kernel(
    const float* __restrict__ x,  const float* __restrict__ xf,
    const float* __restrict__ ln_g,  const float* __restrict__ ln_b,
    const float* __restrict__ tln_g, const float* __restrict__ tln_b,
    const float* __restrict__ Wq, const float* __restrict__ Wk, const float* __restrict__ Wv)
{
    __shared__ float t[32][33];
    const int bid = blockIdx.x;
    const int tid = threadIdx.x;

    if (bid < WCONV_OFF) {
        // ---- LayerNorm path ----
        const float* X;
        const float* gamma;
        const float* beta;
        __half* Y;
        int K, row;
        if (bid < LN_X_BLOCKS) {
            X = x; gamma = ln_g; beta = ln_b; Y = g_xn; K = DD;
            row = bid * 8 + (tid >> 5);
        } else {
            X = xf; gamma = tln_g; beta = tln_b; Y = g_xfn; K = LL;
            row = (bid - LN_X_BLOCKS) * 8 + (tid >> 5);
        }
        int lane = tid & 31;
        const float4* p = (const float4*)(X + (size_t)row * K);
        const int cnt = K >> 7;
        float4 v[4];
        float s = 0.f, sq = 0.f;
        #pragma unroll
        for (int j = 0; j < 4; j++) if (j < cnt) {
            v[j] = p[lane + 32 * j];
            s  += v[j].x + v[j].y + v[j].z + v[j].w;
            sq += v[j].x*v[j].x + v[j].y*v[j].y + v[j].z*v[j].z + v[j].w*v[j].w;
        }
        #pragma unroll
        for (int off = 16; off > 0; off >>= 1) {
            s  += __shfl_xor_sync(0xffffffffu, s,  off);
            sq += __shfl_xor_sync(0xffffffffu, sq, off);
        }
        float mean = s / (float)K;
        float var  = fmaxf(sq / (float)K - mean * mean, 0.f);
        float rstd = rsqrtf(var + 1e-5f);
        uint2* o = (uint2*)(Y + (size_t)row * K);
        #pragma unroll
        for (int j = 0; j < 4; j++) if (j < cnt) {
            int idx = lane + 32 * j;
            float4 g4 = ((const float4*)gamma)[idx];
            float4 b4 = ((const float4*)beta)[idx];
            __half2 h01 = __floats2half2_rn((v[j].x - mean) * rstd * g4.x + b4.x,
                                            (v[j].y - mean) * rstd * g4.y + b4.y);
            __half2 h23 = __floats2half2_rn((v[j].z - mean) * rstd * g4.z + b4.z,
                                            (v[j].w - mean) * rstd * g4.w + b4.w);
            uint2 u;
            u.x = *(uint32_t*)&h01;
            u.y = *(uint32_t*)&h23;
            o[idx] = u;
        }
    } else {
        // ---- weight transpose path: W[K][N] -> WT[N][K] fp16 ----
        int wt = bid - WCONV_OFF;
        const float* W;
        __half* WT;
        int K, nt, kt;
        if (wt < 256)      { W = Wq; WT = g_wqT; K = DD; nt = wt % 16;        kt = wt / 16; }
        else if (wt < 384) { W = Wk; WT = g_wkT; K = LL; nt = (wt-256) % 16;  kt = (wt-256) / 16; }
        else               { W = Wv; WT = g_wvT; K = LL; nt = (wt-384) % 16;  kt = (wt-384) / 16; }
        int nb = nt * 32, kb = kt * 32;
        int tx = tid & 31, ty = tid >> 5;
        for (int i = ty; i < 32; i += 8)
            t[i][tx] = W[(size_t)(kb + i) * DD + nb + tx];
        __syncthreads();
        for (int i = ty; i < 32; i += 8)
            WT[(size_t)(nb + i) * K + kb + tx] = __float2half_rn(t[tx][i]);
    }
}

// ---------------- K2: persistent fp16 tensor GEMM ----------------
#define GBK 64
#define A_BYTES 16384                  // 128 rows x 128B
#define STG_BYTES 32768
#define NSTG 3
#define GEMM_SMEM (NSTG * STG_BYTES)   // 98304

__global__ __launch_bounds__(256, 2) void hgemm(
    const __half* __restrict__ A,
    const __half* __restrict__ BT0, const __half* __restrict__ BT1,
    const float* __restrict__ bias0, const float* __restrict__ bias1,
    __half* __restrict__ C0, __half* __restrict__ C1,
    int M, int K, int KT, int ntiles, int tiles_per_w)
{
    extern __shared__ char smraw[];
    const uint32_t sb = smem_u32(smraw);
    const int tid  = threadIdx.x;
    const int wid  = tid >> 5;
    const int lane = tid & 31;
    const int wm = wid & 3;
    const int wn = wid >> 2;
    const int g  = lane >> 2;
    const int tg = lane & 3;
    const int blk = lane >> 3;
    const int rin = lane & 7;
    const int G = (int)gridDim.x;

    int t_l = blockIdx.x, kt_l = 0;

    auto load_step = [&](int st) {
        if (t_l < ntiles) {
            int w = (t_l >= tiles_per_w) ? 1 : 0;
            int r = t_l - (w ? tiles_per_w : 0);
            int m0 = (r >> 2) * 128;
            int n0 = (r & 3) * 128;
            const __half* Bt = w ? BT1 : BT0;
            uint32_t base = sb + st * STG_BYTES;
            #pragma unroll
            for (int i = 0; i < 4; i++) {
                int id = tid + i * 256;
                int row = id >> 3, c = id & 7;
                int m = m0 + row;
                if (m >= M) m = M - 1;
                cp_async16(base + row * 128 + ((c ^ (row & 7)) << 4),
                           A + (size_t)m * K + kt_l * GBK + c * 8);
            }
            #pragma unroll
            for (int i = 0; i < 4; i++) {
                int id = tid + i * 256;
                int row = id >> 3, c = id & 7;
                cp_async16(base + A_BYTES + row * 128 + ((c ^ (row & 7)) << 4),
                           Bt + (size_t)(n0 + row) * K + kt_l * GBK + c * 8);
            }
        }
        asm volatile("cp.async.commit_group;" ::: "memory");
        if (++kt_l == KT) { kt_l = 0; t_l += G; }
    };

    float acc[2][8][4];
    #pragma unroll
    for (int mt = 0; mt < 2; mt++)
        #pragma unroll
        for (int nt = 0; nt < 8; nt++)
            #pragma unroll
            for (int j = 0; j < 4; j++) acc[mt][nt][j] = 0.f;

    load_step(0);
    load_step(1);

    int stage = 0;
    int t_c = blockIdx.x, kt_c = 0;

    while (t_c < ntiles) {
        asm volatile("cp.async.wait_group 1;" ::: "memory");
        __syncthreads();
        const uint32_t aB = sb + stage * STG_BYTES;
        const uint32_t bB = aB + A_BYTES;

        #pragma unroll
        for (int ks = 0; ks < 4; ks++) {
            uint32_t af[2][4];
            #pragma unroll
            for (int mt = 0; mt < 2; mt++) {
                int row = wm * 32 + mt * 16 + ((blk & 1) << 3) + rin;
                int ch  = 2 * ks + (blk >> 1);
                ldm4(af[mt], aB + row * 128 + ((ch ^ (row & 7)) << 4));
            }
            #pragma unroll
            for (int np = 0; np < 4; np++) {
                uint32_t bf[4];
                int nr = wn * 64 + np * 16 + ((blk >> 1) << 3) + rin;
                int ch = 2 * ks + (blk & 1);
                ldm4(bf, bB + nr * 128 + ((ch ^ (nr & 7)) << 4));
                mma_fp16(acc[0][np*2  ], af[0][0], af[0][1], af[0][2], af[0][3], bf[0], bf[1]);
                mma_fp16(acc[0][np*2+1], af[0][0], af[0][1], af[0][2], af[0][3], bf[2], bf[3]);
                mma_fp16(acc[1][np*2  ], af[1][0], af[1][1], af[1][2], af[1][3], bf[0], bf[1]);
                mma_fp16(acc[1][np*2+1], af[1][0], af[1][1], af[1][2], af[1][3], bf[2], bf[3]);
            }
        }

        int nst = stage + 2;
        if (nst >= NSTG) nst -= NSTG;
        load_step(nst);

        if (++kt_c == KT) {
            int w = (t_c >= tiles_per_w) ? 1 : 0;
            int r = t_c - (w ? tiles_per_w : 0);
            int m0 = (r >> 2) * 128;
            int n0 = (r & 3) * 128;
            const float* bias = w ? bias1 : bias0;
            __half* C = w ? C1 : C0;
            #pragma unroll
            for (int mt = 0; mt < 2; mt++) {
                int r0 = m0 + wm * 32 + mt * 16 + g;
                #pragma unroll
                for (int nt = 0; nt < 8; nt++) {
                    int col = n0 + wn * 64 + nt * 8 + 2 * tg;
                    float b0 = bias[col], b1 = bias[col + 1];
                    if (r0 < M) {
                        __half2 h = __floats2half2_rn(acc[mt][nt][0] + b0, acc[mt][nt][1] + b1);
                        *(uint32_t*)(C + (size_t)r0 * DD + col) = *(uint32_t*)&h;
                    }
                    if (r0 + 8 < M) {
                        __half2 h = __floats2half2_rn(acc[mt][nt][2] + b0, acc[mt][nt][3] + b1);
                        *(uint32_t*)(C + (size_t)(r0 + 8) * DD + col) = *(uint32_t*)&h;
                    }
                    acc[mt][nt][0] = 0.f; acc[mt][nt][1] = 0.f;
                    acc[mt][nt][2] = 0.f; acc[mt][nt][3] = 0.f;
                }
            }
            kt_c = 0;
            t_c += G;
        }
        if (++stage == NSTG) stage = 0;
    }
}

// ---------------- K3: fused attention, one head per CTA, ldmatrix + reg-resident P ----------------
// grid (T/128, B, H) = (8, 32, 8); 256 threads, warp owns 16 t-rows.
#define LDQ 72
#define LDK 72
#define LDV 72

__global__ __launch_bounds__(256) void attn_kernel(
    const __half* __restrict__ q, const __half* __restrict__ k,
    const __half* __restrict__ v, float* __restrict__ out)
{
    __shared__ __align__(16) __half s_q[128 * LDQ];
    __shared__ __align__(16) __half s_k[80 * LDK];
    __shared__ __align__(16) __half s_v[80 * LDV];

    const int b  = blockIdx.y;
    const int t0 = blockIdx.x * 128;
    const int h  = blockIdx.z;
    const int tid  = threadIdx.x;
    const int wid  = tid >> 5;
    const int lane = tid & 31;
    const int g  = lane >> 2;
    const int tg = lane & 3;
    const int blk = lane >> 3;
    const int rin = lane & 7;
    const int rb = wid * 16;
    const float scale = 0.125f;

    const uint32_t sq = smem_u32(s_q);
    const uint32_t sk = smem_u32(s_k);
    const uint32_t sv = smem_u32(s_v);

    // ---- stage q: 128 rows x 8 x 16B ----
    #pragma unroll
    for (int i = 0; i < 4; i++) {
        int s = tid + i * 256;
        int r = s >> 3, c = s & 7;
        uint4 u = *(const uint4*)(q + (size_t)(b * TT + t0 + r) * DD + h * HD + c * 8);
        *(uint4*)(s_q + r * LDQ + c * 8) = u;
    }
    // ---- stage k & v row-major: 80 rows, zero-pad >= 77 ----
    for (int s = tid; s < 80 * 8; s += 256) {
        int n = s >> 3, c = s & 7;
        uint4 uk = make_uint4(0u, 0u, 0u, 0u);
        uint4 uv = make_uint4(0u, 0u, 0u, 0u);
        if (n < NN) {
            size_t base = (size_t)(b * NN + n) * DD + h * HD + c * 8;
            uk = *(const uint4*)(k + base);
            uv = *(const uint4*)(v + base);
        }
        *(uint4*)(s_k + n * LDK + c * 8) = uk;
        *(uint4*)(s_v + n * LDV + c * 8) = uv;
    }
    __syncthreads();

    // ---- S = q @ k^T : 16 x 80 per warp, K=64, all ldmatrix ----
    float sacc[10][4];
    #pragma unroll
    for (int nt = 0; nt < 10; nt++)
        #pragma unroll
        for (int j = 0; j < 4; j++) sacc[nt][j] = 0.f;

    #pragma unroll
    for (int ks = 0; ks < 4; ks++) {
        uint32_t af[4];
        {
            int row = rb + ((blk & 1) << 3) + rin;
            int col = ks * 16 + ((blk >> 1) << 3);
            ldm4(af, sq + (row * LDQ + col) * 2);
        }
        #pragma unroll
        for (int nt16 = 0; nt16 < 5; nt16++) {
            uint32_t bf[4];
            int nr  = nt16 * 16 + ((blk >> 1) << 3) + rin;
            int col = ks * 16 + ((blk & 1) << 3);
            ldm4(bf, sk + (nr * LDK + col) * 2);
            mma_fp16(sacc[nt16*2  ], af[0], af[1], af[2], af[3], bf[0], bf[1]);
            mma_fp16(sacc[nt16*2+1], af[0], af[1], af[2], af[3], bf[2], bf[3]);
        }
    }

    // ---- masked softmax over tokens (cols >= 77 masked) ----
    float mx0 = -1e30f, mx1 = -1e30f;
    #pragma unroll
    for (int nt = 0; nt < 10; nt++) {
        int c0 = nt * 8 + 2 * tg;
        sacc[nt][0] = (c0     < NN) ? sacc[nt][0] * scale : -1e30f;
        sacc[nt][1] = (c0 + 1 < NN) ? sacc[nt][1] * scale : -1e30f;
        sacc[nt][2] = (c0     < NN) ? sacc[nt][2] * scale : -1e30f;
        sacc[nt][3] = (c0 + 1 < NN) ? sacc[nt][3] * scale : -1e30f;
        mx0 = fmaxf(mx0, fmaxf(sacc[nt][0], sacc[nt][1]));
        mx1 = fmaxf(mx1, fmaxf(sacc[nt][2], sacc[nt][3]));
    }
    mx0 = fmaxf(mx0, __shfl_xor_sync(0xffffffffu, mx0, 1));
    mx0 = fmaxf(mx0, __shfl_xor_sync(0xffffffffu, mx0, 2));
    mx1 = fmaxf(mx1, __shfl_xor_sync(0xffffffffu, mx1, 1));
    mx1 = fmaxf(mx1, __shfl_xor_sync(0xffffffffu, mx1, 2));

    float s0 = 0.f, s1 = 0.f;
    #pragma unroll
    for (int nt = 0; nt < 10; nt++) {
        sacc[nt][0] = __expf(sacc[nt][0] - mx0);
        sacc[nt][1] = __expf(sacc[nt][1] - mx0);
        sacc[nt][2] = __expf(sacc[nt][2] - mx1);
        sacc[nt][3] = __expf(sacc[nt][3] - mx1);
        s0 += sacc[nt][0] + sacc[nt][1];
        s1 += sacc[nt][2] + sacc[nt][3];
    }
    s0 += __shfl_xor_sync(0xffffffffu, s0, 1);
    s0 += __shfl_xor_sync(0xffffffffu, s0, 2);
    s1 += __shfl_xor_sync(0xffffffffu, s1, 1);
    s1 += __shfl_xor_sync(0xffffffffu, s1, 2);
    const float inv0 = 1.0f / s0;
    const float inv1 = 1.0f / s1;

    // ---- Y = P @ V : P stays in registers (c-frag == a-frag layout) ----
    float yacc[8][4];
    #pragma unroll
    for (int nt = 0; nt < 8; nt++)
        #pragma unroll
        for (int j = 0; j < 4; j++) yacc[nt][j] = 0.f;

    #pragma unroll
    for (int ks = 0; ks < 5; ks++) {     // 5 chunks of 16 tokens
        __half2 ha0 = __floats2half2_rn(sacc[2*ks  ][0] * inv0, sacc[2*ks  ][1] * inv0);
        __half2 ha1 = __floats2half2_rn(sacc[2*ks  ][2] * inv1, sacc[2*ks  ][3] * inv1);
        __half2 ha2 = __floats2half2_rn(sacc[2*ks+1][0] * inv0, sacc[2*ks+1][1] * inv0);
        __half2 ha3 = __floats2half2_rn(sacc[2*ks+1][2] * inv1, sacc[2*ks+1][3] * inv1);
        uint32_t a0 = *(uint32_t*)&ha0;
        uint32_t a1 = *(uint32_t*)&ha1;
        uint32_t a2 = *(uint32_t*)&ha2;
        uint32_t a3 = *(uint32_t*)&ha3;
        #pragma unroll
        for (int dt = 0; dt < 4; dt++) { // 4 chunks of 16 d-cols
            uint32_t bf[4];
            int tr = ks * 16 + ((blk & 1) << 3) + rin;   // token row
            int dc = dt * 16 + ((blk >> 1) << 3);        // d col
            ldm4t(bf, sv + (tr * LDV + dc) * 2);
            mma_fp16(yacc[dt*2  ], a0, a1, a2, a3, bf[0], bf[1]);
            mma_fp16(yacc[dt*2+1], a0, a1, a2, a3, bf[2], bf[3]);
        }
    }

    // ---- write y (fp32) ----
    #pragma unroll
    for (int nt = 0; nt < 8; nt++) {
        int col = h * HD + nt * 8 + 2 * tg;
        size_t row0 = (size_t)(b * TT + t0 + rb + g);
        *(float2*)(out + row0 * DD + col) = make_float2(yacc[nt][0], yacc[nt][1]);
        *(float2*)(out + (row0 + 8) * DD + col) = make_float2(yacc[nt][2], yacc[nt][3]);
    }
}

// ---------------- launch ----------------
extern "C" void kernel_launch(void* const* d_in, const int* in_sizes, int n_in,
                              void* d_out, int out_size) {
    const float* x     = (const float*)d_in[0];
    const float* xf    = (const float*)d_in[1];
    const float* ln_g  = (const float*)d_in[2];
    const float* ln_b  = (const float*)d_in[3];
    const float* tln_g = (const float*)d_in[4];
    const float* tln_b = (const float*)d_in[5];
    const float* Wq    = (const float*)d_in[6];
    const float* bq    = (const float*)d_in[7];
    const float* Wk    = (const float*)d_in[8];
    const float* bk    = (const float*)d_in[9];
    const float* Wv    = (const float*)d_in[10];
    const float* bv    = (const float*)d_in[11];
    float* out = (float*)d_out;

    void *p_xn, *p_xfn, *p_wqT, *p_wkT, *p_wvT, *p_q, *p_k, *p_v;
    cudaGetSymbolAddress(&p_xn,  g_xn);
    cudaGetSymbolAddress(&p_xfn, g_xfn);
    cudaGetSymbolAddress(&p_wqT, g_wqT);
    cudaGetSymbolAddress(&p_wkT, g_wkT);
    cudaGetSymbolAddress(&p_wvT, g_wvT);
    cudaGetSymbolAddress(&p_q,   g_q);
    cudaGetSymbolAddress(&p_k,   g_k);
    cudaGetSymbolAddress(&p_v,   g_v);

    cudaFuncSetAttribute(hgemm, cudaFuncAttributeMaxDynamicSharedMemorySize, GEMM_SMEM);

    // 1) prep: both LayerNorms + all three weight transposes
    prep_kernel<<<PREP_BLOCKS, 256>>>(x, xf, ln_g, ln_b, tln_g, tln_b, Wq, Wk, Wv);

    // 2) q = xn @ Wq + bq : 1024 tiles, persistent over 296 CTAs
    hgemm<<<296, 256, GEMM_SMEM>>>(
        (const __half*)p_xn, (const __half*)p_wqT, (const __half*)p_wqT,
        bq, bq, (__half*)p_q, (__half*)p_q,
        M_X, DD, DD / GBK, 1024, 1024);

    // 3) k,v = xfn @ {Wk,Wv} : 80 tiles each, one launch
    hgemm<<<160, 256, GEMM_SMEM>>>(
        (const __half*)p_xfn, (const __half*)p_wkT, (const __half*)p_wvT,
        bk, bv, (__half*)p_k, (__half*)p_v,
        M_XF, LL, LL / GBK, 160, 80);

    // 4) attention: one head per CTA
    attn_kernel<<<dim3(TT / 128, BB, HH), 256>>>((const __half*)p_q, (const __half*)p_k,
                                                 (const __half*)p_v, out);
}

// round 10
// speedup vs baseline: 2.7576x; 1.0144x over previous
#include <cuda_runtime.h>
#include <cuda_fp16.h>
#include <cstdint>
#include <cstddef>

// ---------------- problem constants ----------------
#define BB   32
#define TT   1024
#define NN   77
#define DD   512
#define LL   256
#define HH   8
#define HD   64
#define M_X  (BB*TT)          // 32768 rows of x
#define M_XF (BB*NN)          // 2464 rows of xf

// ---------------- scratch (static device, no allocation) ----------------
__device__ __half g_xn [(size_t)M_X * DD];    // 32 MB  LN(x) fp16
__device__ __half g_xfn[(size_t)M_XF * LL];
__device__ __half g_wqT[DD * DD];             // [N][K] fp16 (K-major)
__device__ __half g_wkT[DD * LL];
__device__ __half g_wvT[DD * LL];
__device__ __half g_k[(size_t)M_XF * DD];
__device__ __half g_v[(size_t)M_XF * DD];

// ---------------- primitives ----------------
__device__ __forceinline__ uint32_t smem_u32(const void* p) {
    return (uint32_t)__cvta_generic_to_shared(p);
}
__device__ __forceinline__ void mma_fp16(float* c,
                                         uint32_t a0, uint32_t a1, uint32_t a2, uint32_t a3,
                                         uint32_t b0, uint32_t b1) {
    asm volatile(
        "mma.sync.aligned.m16n8k16.row.col.f32.f16.f16.f32 "
        "{%0,%1,%2,%3}, {%4,%5,%6,%7}, {%8,%9}, {%0,%1,%2,%3};"
        : "+f"(c[0]), "+f"(c[1]), "+f"(c[2]), "+f"(c[3])
        : "r"(a0), "r"(a1), "r"(a2), "r"(a3), "r"(b0), "r"(b1));
}
__device__ __forceinline__ void ldm4(uint32_t* r, uint32_t addr) {
    asm volatile("ldmatrix.sync.aligned.m8n8.x4.shared.b16 {%0,%1,%2,%3}, [%4];"
                 : "=r"(r[0]), "=r"(r[1]), "=r"(r[2]), "=r"(r[3]) : "r"(addr));
}
__device__ __forceinline__ void ldm4t(uint32_t* r, uint32_t addr) {
    asm volatile("ldmatrix.sync.aligned.m8n8.x4.trans.shared.b16 {%0,%1,%2,%3}, [%4];"
                 : "=r"(r[0]), "=r"(r[1]), "=r"(r[2]), "=r"(r[3]) : "r"(addr));
}
__device__ __forceinline__ void cp_async16(uint32_t dst, const void* src) {
    asm volatile("cp.async.cg.shared.global [%0], [%1], 16;"
                 :: "r"(dst), "l"(src) : "memory");
}
__device__ __forceinline__ void cp_async16z(uint32_t dst, const void* src, int src_bytes) {
    asm volatile("cp.async.cg.shared.global [%0], [%1], 16, %2;"
                 :: "r"(dst), "l"(src), "r"(src_bytes) : "memory");
}

// ---------------- K1: prep = LN(x) + LN(xf) + 3 weight transposes ----------------
#define LN_X_BLOCKS   (M_X / 8)            // 4096
#define LN_XF_BLOCKS  (M_XF / 8)           // 308
#define WCONV_OFF     (LN_X_BLOCKS + LN_XF_BLOCKS)   // 4404
#define PREP_BLOCKS   (WCONV_OFF + 512)

__global__ __launch_bounds__(256) void prep_kernel(
    const float* __restrict__ x,  const float* __restrict__ xf,
    const float* __restrict__ ln_g,  const float* __restrict__ ln_b,
    const float* __restrict__ tln_g, const float* __restrict__ tln_b,
    const float* __restrict__ Wq, const float* __restrict__ Wk, const float* __restrict__ Wv)
{
    __shared__ float t[32][33];
    const int bid = blockIdx.x;
    const int tid = threadIdx.x;

    if (bid < WCONV_OFF) {
        const float* X;
        const float* gamma;
        const float* beta;
        __half* Y;
        int K, row;
        if (bid < LN_X_BLOCKS) {
            X = x; gamma = ln_g; beta = ln_b; Y = g_xn; K = DD;
            row = bid * 8 + (tid >> 5);
        } else {
            X = xf; gamma = tln_g; beta = tln_b; Y = g_xfn; K = LL;
            row = (bid - LN_X_BLOCKS) * 8 + (tid >> 5);
        }
        int lane = tid & 31;
        const float4* p = (const float4*)(X + (size_t)row * K);
        const int cnt = K >> 7;
        float4 v[4];
        float s = 0.f, sq = 0.f;
        #pragma unroll
        for (int j = 0; j < 4; j++) if (j < cnt) {
            v[j] = p[lane + 32 * j];
            s  += v[j].x + v[j].y + v[j].z + v[j].w;
            sq += v[j].x*v[j].x + v[j].y*v[j].y + v[j].z*v[j].z + v[j].w*v[j].w;
        }
        #pragma unroll
        for (int off = 16; off > 0; off >>= 1) {
            s  += __shfl_xor_sync(0xffffffffu, s,  off);
            sq += __shfl_xor_sync(0xffffffffu, sq, off);
        }
        float mean = s / (float)K;
        float var  = fmaxf(sq / (float)K - mean * mean, 0.f);
        float rstd = rsqrtf(var + 1e-5f);
        uint2* o = (uint2*)(Y + (size_t)row * K);
        #pragma unroll
        for (int j = 0; j < 4; j++) if (j < cnt) {
            int idx = lane + 32 * j;
            float4 g4 = ((const float4*)gamma)[idx];
            float4 b4 = ((const float4*)beta)[idx];
            __half2 h01 = __floats2half2_rn((v[j].x - mean) * rstd * g4.x + b4.x,
                                            (v[j].y - mean) * rstd * g4.y + b4.y);
            __half2 h23 = __floats2half2_rn((v[j].z - mean) * rstd * g4.z + b4.z,
                                            (v[j].w - mean) * rstd * g4.w + b4.w);
            uint2 u;
            u.x = *(uint32_t*)&h01;
            u.y = *(uint32_t*)&h23;
            o[idx] = u;
        }
    } else {
        int wt = bid - WCONV_OFF;
        const float* W;
        __half* WT;
        int K, nt, kt;
        if (wt < 256)      { W = Wq; WT = g_wqT; K = DD; nt = wt % 16;        kt = wt / 16; }
        else if (wt < 384) { W = Wk; WT = g_wkT; K = LL; nt = (wt-256) % 16;  kt = (wt-256) / 16; }
        else               { W = Wv; WT = g_wvT; K = LL; nt = (wt-384) % 16;  kt = (wt-384) / 16; }
        int nb = nt * 32, kb = kt * 32;
        int tx = tid & 31, ty = tid >> 5;
        for (int i = ty; i < 32; i += 8)
            t[i][tx] = W[(size_t)(kb + i) * DD + nb + tx];
        __syncthreads();
        for (int i = ty; i < 32; i += 8)
            WT[(size_t)(nb + i) * K + kb + tx] = __float2half_rn(t[tx][i]);
    }
}

// ---------------- K2: persistent fp16 tensor GEMM (k/v only) ----------------
#define GBK 64
#define A_BYTES 16384
#define STG_BYTES 32768
#define NSTG 3
#define GEMM_SMEM (NSTG * STG_BYTES)

__global__ __launch_bounds__(256, 2) void hgemm(
    const __half* __restrict__ A,
    const __half* __restrict__ BT0, const __half* __restrict__ BT1,
    const float* __restrict__ bias0, const float* __restrict__ bias1,
    __half* __restrict__ C0, __half* __restrict__ C1,
    int M, int K, int KT, int ntiles, int tiles_per_w)
{
    extern __shared__ char smraw[];
    const uint32_t sb = smem_u32(smraw);
    const int tid  = threadIdx.x;
    const int wid  = tid >> 5;
    const int lane = tid & 31;
    const int wm = wid & 3;
    const int wn = wid >> 2;
    const int g  = lane >> 2;
    const int tg = lane & 3;
    const int blk = lane >> 3;
    const int rin = lane & 7;
    const int G = (int)gridDim.x;

    int t_l = blockIdx.x, kt_l = 0;

    auto load_step = [&](int st) {
        if (t_l < ntiles) {
            int w = (t_l >= tiles_per_w) ? 1 : 0;
            int r = t_l - (w ? tiles_per_w : 0);
            int m0 = (r >> 2) * 128;
            int n0 = (r & 3) * 128;
            const __half* Bt = w ? BT1 : BT0;
            uint32_t base = sb + st * STG_BYTES;
            #pragma unroll
            for (int i = 0; i < 4; i++) {
                int id = tid + i * 256;
                int row = id >> 3, c = id & 7;
                int m = m0 + row;
                if (m >= M) m = M - 1;
                cp_async16(base + row * 128 + ((c ^ (row & 7)) << 4),
                           A + (size_t)m * K + kt_l * GBK + c * 8);
            }
            #pragma unroll
            for (int i = 0; i < 4; i++) {
                int id = tid + i * 256;
                int row = id >> 3, c = id & 7;
                cp_async16(base + A_BYTES + row * 128 + ((c ^ (row & 7)) << 4),
                           Bt + (size_t)(n0 + row) * K + kt_l * GBK + c * 8);
            }
        }
        asm volatile("cp.async.commit_group;" ::: "memory");
        if (++kt_l == KT) { kt_l = 0; t_l += G; }
    };

    float acc[2][8][4];
    #pragma unroll
    for (int mt = 0; mt < 2; mt++)
        #pragma unroll
        for (int nt = 0; nt < 8; nt++)
            #pragma unroll
            for (int j = 0; j < 4; j++) acc[mt][nt][j] = 0.f;

    load_step(0);
    load_step(1);

    int stage = 0;
    int t_c = blockIdx.x, kt_c = 0;

    while (t_c < ntiles) {
        asm volatile("cp.async.wait_group 1;" ::: "memory");
        __syncthreads();
        const uint32_t aB = sb + stage * STG_BYTES;
        const uint32_t bB = aB + A_BYTES;

        #pragma unroll
        for (int ks = 0; ks < 4; ks++) {
            uint32_t af[2][4];
            #pragma unroll
            for (int mt = 0; mt < 2; mt++) {
                int row = wm * 32 + mt * 16 + ((blk & 1) << 3) + rin;
                int ch  = 2 * ks + (blk >> 1);
                ldm4(af[mt], aB + row * 128 + ((ch ^ (row & 7)) << 4));
            }
            #pragma unroll
            for (int np = 0; np < 4; np++) {
                uint32_t bf[4];
                int nr = wn * 64 + np * 16 + ((blk >> 1) << 3) + rin;
                int ch = 2 * ks + (blk & 1);
                ldm4(bf, bB + nr * 128 + ((ch ^ (nr & 7)) << 4));
                mma_fp16(acc[0][np*2  ], af[0][0], af[0][1], af[0][2], af[0][3], bf[0], bf[1]);
                mma_fp16(acc[0][np*2+1], af[0][0], af[0][1], af[0][2], af[0][3], bf[2], bf[3]);
                mma_fp16(acc[1][np*2  ], af[1][0], af[1][1], af[1][2], af[1][3], bf[0], bf[1]);
                mma_fp16(acc[1][np*2+1], af[1][0], af[1][1], af[1][2], af[1][3], bf[2], bf[3]);
            }
        }

        int nst = stage + 2;
        if (nst >= NSTG) nst -= NSTG;
        load_step(nst);

        if (++kt_c == KT) {
            int w = (t_c >= tiles_per_w) ? 1 : 0;
            int r = t_c - (w ? tiles_per_w : 0);
            int m0 = (r >> 2) * 128;
            int n0 = (r & 3) * 128;
            const float* bias = w ? bias1 : bias0;
            __half* C = w ? C1 : C0;
            #pragma unroll
            for (int mt = 0; mt < 2; mt++) {
                int r0 = m0 + wm * 32 + mt * 16 + g;
                #pragma unroll
                for (int nt = 0; nt < 8; nt++) {
                    int col = n0 + wn * 64 + nt * 8 + 2 * tg;
                    float b0 = bias[col], b1 = bias[col + 1];
                    if (r0 < M) {
                        __half2 h = __floats2half2_rn(acc[mt][nt][0] + b0, acc[mt][nt][1] + b1);
                        *(uint32_t*)(C + (size_t)r0 * DD + col) = *(uint32_t*)&h;
                    }
                    if (r0 + 8 < M) {
                        __half2 h = __floats2half2_rn(acc[mt][nt][2] + b0, acc[mt][nt][3] + b1);
                        *(uint32_t*)(C + (size_t)(r0 + 8) * DD + col) = *(uint32_t*)&h;
                    }
                    acc[mt][nt][0] = 0.f; acc[mt][nt][1] = 0.f;
                    acc[mt][nt][2] = 0.f; acc[mt][nt][3] = 0.f;
                }
            }
            kt_c = 0;
            t_c += G;
        }
        if (++stage == NSTG) stage = 0;
    }
}

// ---------------- K3: fused qGEMM + attention ----------------
// grid (H, T/128, B) = (8, 8, 32); 256 threads, warp owns 16 t-rows.
// q computed in registers: stream xn/WqT k-chunks; q c-frag == S a-frag layout.
#define FLDX 72
#define FLDW 72
#define FLDK 72
#define FLDV 72
#define SX_BYTES (128 * FLDX * 2)         // 18432
#define SW_BYTES (64 * FLDW * 2)          // 9216
#define OFF_SW   (2 * SX_BYTES)           // 36864
#define OFF_SK   (OFF_SW + 2 * SW_BYTES)  // 55296
#define OFF_SV   (OFF_SK + 80 * FLDK * 2) // 66816
#define FUSED_SMEM (OFF_SV + 80 * FLDV * 2)  // 78336

__global__ __launch_bounds__(256) void fused_qattn(
    const __half* __restrict__ xn, const __half* __restrict__ wqT,
    const float* __restrict__ bq,
    const __half* __restrict__ k, const __half* __restrict__ v,
    float* __restrict__ out)
{
    extern __shared__ char smraw[];
    const uint32_t sb = smem_u32(smraw);
    const uint32_t sx = sb;
    const uint32_t sw = sb + OFF_SW;
    const uint32_t sk = sb + OFF_SK;
    const uint32_t sv = sb + OFF_SV;

    const int h  = blockIdx.x;
    const int t0 = blockIdx.y * 128;
    const int b  = blockIdx.z;
    const int tid  = threadIdx.x;
    const int wid  = tid >> 5;
    const int lane = tid & 31;
    const int g  = lane >> 2;
    const int tg = lane & 3;
    const int blk = lane >> 3;
    const int rin = lane & 7;
    const int rb = wid * 16;
    const float scale = 0.125f;

    auto load_chunk = [&](int buf, int kt) {
        uint32_t xb = sx + buf * SX_BYTES;
        #pragma unroll
        for (int i = 0; i < 4; i++) {
            int id = tid + i * 256;
            int r = id >> 3, c = id & 7;
            cp_async16(xb + (r * FLDX + c * 8) * 2,
                       xn + (size_t)(b * TT + t0 + r) * DD + kt * 64 + c * 8);
        }
        uint32_t wb = sw + buf * SW_BYTES;
        #pragma unroll
        for (int i = 0; i < 2; i++) {
            int id = tid + i * 256;
            int r = id >> 3, c = id & 7;
            cp_async16(wb + (r * FLDW + c * 8) * 2,
                       wqT + (size_t)(h * HD + r) * DD + kt * 64 + c * 8);
        }
    };

    // ---- prologue: kv + chunk0 in group0, chunk1 in group1 ----
    for (int s = tid; s < 80 * 8; s += 256) {
        int n = s >> 3, c = s & 7;
        int ok = (n < NN) ? 16 : 0;
        size_t base = (size_t)(b * NN + ((n < NN) ? n : 0)) * DD + h * HD + c * 8;
        cp_async16z(sk + (n * FLDK + c * 8) * 2, k + base, ok);
        cp_async16z(sv + (n * FLDV + c * 8) * 2, v + base, ok);
    }
    load_chunk(0, 0);
    asm volatile("cp.async.commit_group;" ::: "memory");
    load_chunk(1, 1);
    asm volatile("cp.async.commit_group;" ::: "memory");

    // ---- q = xn @ WqT^T : warp computes rows rb..rb+15 x 64 cols, K=512 ----
    float qacc[8][4];
    #pragma unroll
    for (int nt = 0; nt < 8; nt++)
        #pragma unroll
        for (int j = 0; j < 4; j++) qacc[nt][j] = 0.f;

    for (int kt = 0; kt < 8; kt++) {
        asm volatile("cp.async.wait_group 1;" ::: "memory");
        __syncthreads();
        const uint32_t xb = sx + (kt & 1) * SX_BYTES;
        const uint32_t wb = sw + (kt & 1) * SW_BYTES;
        #pragma unroll
        for (int ks = 0; ks < 4; ks++) {
            uint32_t af[4];
            {
                int row = rb + ((blk & 1) << 3) + rin;
                int col = ks * 16 + ((blk >> 1) << 3);
                ldm4(af, xb + (row * FLDX + col) * 2);
            }
            #pragma unroll
            for (int np = 0; np < 4; np++) {
                uint32_t bf[4];
                int nr = np * 16 + ((blk >> 1) << 3) + rin;
                int bc = ks * 16 + ((blk & 1) << 3);
                ldm4(bf, wb + (nr * FLDW + bc) * 2);
                mma_fp16(qacc[np*2  ], af[0], af[1], af[2], af[3], bf[0], bf[1]);
                mma_fp16(qacc[np*2+1], af[0], af[1], af[2], af[3], bf[2], bf[3]);
            }
        }
        __syncthreads();   // all warps done reading this buffer
        if (kt + 2 < 8) load_chunk(kt & 1, kt + 2);
        asm volatile("cp.async.commit_group;" ::: "memory");
    }

    // ---- + bias, fold softmax scale, pack q into a-frags ----
    uint32_t qa[4][4];
    #pragma unroll
    for (int nt = 0; nt < 8; nt++) {
        int col = h * HD + nt * 8 + 2 * tg;
        float b0 = bq[col], b1 = bq[col + 1];
        qacc[nt][0] = (qacc[nt][0] + b0) * scale;
        qacc[nt][1] = (qacc[nt][1] + b1) * scale;
        qacc[nt][2] = (qacc[nt][2] + b0) * scale;
        qacc[nt][3] = (qacc[nt][3] + b1) * scale;
    }
    #pragma unroll
    for (int ks = 0; ks < 4; ks++) {
        __half2 a0 = __floats2half2_rn(qacc[2*ks  ][0], qacc[2*ks  ][1]);
        __half2 a1 = __floats2half2_rn(qacc[2*ks  ][2], qacc[2*ks  ][3]);
        __half2 a2 = __floats2half2_rn(qacc[2*ks+1][0], qacc[2*ks+1][1]);
        __half2 a3 = __floats2half2_rn(qacc[2*ks+1][2], qacc[2*ks+1][3]);
        qa[ks][0] = *(uint32_t*)&a0;
        qa[ks][1] = *(uint32_t*)&a1;
        qa[ks][2] = *(uint32_t*)&a2;
        qa[ks][3] = *(uint32_t*)&a3;
    }

    // ---- S = q @ k^T : 16 x 80 per warp ----
    float sacc[10][4];
    #pragma unroll
    for (int nt = 0; nt < 10; nt++)
        #pragma unroll
        for (int j = 0; j < 4; j++) sacc[nt][j] = 0.f;

    #pragma unroll
    for (int ks = 0; ks < 4; ks++) {
        #pragma unroll
        for (int nt16 = 0; nt16 < 5; nt16++) {
            uint32_t bf[4];
            int nr  = nt16 * 16 + ((blk >> 1) << 3) + rin;
            int col = ks * 16 + ((blk & 1) << 3);
            ldm4(bf, sk + (nr * FLDK + col) * 2);
            mma_fp16(sacc[nt16*2  ], qa[ks][0], qa[ks][1], qa[ks][2], qa[ks][3], bf[0], bf[1]);
            mma_fp16(sacc[nt16*2+1], qa[ks][0], qa[ks][1], qa[ks][2], qa[ks][3], bf[2], bf[3]);
        }
    }

    // ---- masked softmax over tokens (cols >= 77 masked; scale already folded) ----
    float mx0 = -1e30f, mx1 = -1e30f;
    #pragma unroll
    for (int nt = 0; nt < 10; nt++) {
        int c0 = nt * 8 + 2 * tg;
        if (c0     >= NN) { sacc[nt][0] = -1e30f; sacc[nt][2] = -1e30f; }
        if (c0 + 1 >= NN) { sacc[nt][1] = -1e30f; sacc[nt][3] = -1e30f; }
        mx0 = fmaxf(mx0, fmaxf(sacc[nt][0], sacc[nt][1]));
        mx1 = fmaxf(mx1, fmaxf(sacc[nt][2], sacc[nt][3]));
    }
    mx0 = fmaxf(mx0, __shfl_xor_sync(0xffffffffu, mx0, 1));
    mx0 = fmaxf(mx0, __shfl_xor_sync(0xffffffffu, mx0, 2));
    mx1 = fmaxf(mx1, __shfl_xor_sync(0xffffffffu, mx1, 1));
    mx1 = fmaxf(mx1, __shfl_xor_sync(0xffffffffu, mx1, 2));

    float s0 = 0.f, s1 = 0.f;
    #pragma unroll
    for (int nt = 0; nt < 10; nt++) {
        sacc[nt][0] = __expf(sacc[nt][0] - mx0);
        sacc[nt][1] = __expf(sacc[nt][1] - mx0);
        sacc[nt][2] = __expf(sacc[nt][2] - mx1);
        sacc[nt][3] = __expf(sacc[nt][3] - mx1);
        s0 += sacc[nt][0] + sacc[nt][1];
        s1 += sacc[nt][2] + sacc[nt][3];
    }
    s0 += __shfl_xor_sync(0xffffffffu, s0, 1);
    s0 += __shfl_xor_sync(0xffffffffu, s0, 2);
    s1 += __shfl_xor_sync(0xffffffffu, s1, 1);
    s1 += __shfl_xor_sync(0xffffffffu, s1, 2);
    const float inv0 = 1.0f / s0;
    const float inv1 = 1.0f / s1;

    // ---- Y = P @ V : P register-resident ----
    float yacc[8][4];
    #pragma unroll
    for (int nt = 0; nt < 8; nt++)
        #pragma unroll
        for (int j = 0; j < 4; j++) yacc[nt][j] = 0.f;

    #pragma unroll
    for (int ks = 0; ks < 5; ks++) {
        __half2 ha0 = __floats2half2_rn(sacc[2*ks  ][0] * inv0, sacc[2*ks  ][1] * inv0);
        __half2 ha1 = __floats2half2_rn(sacc[2*ks  ][2] * inv1, sacc[2*ks  ][3] * inv1);
        __half2 ha2 = __floats2half2_rn(sacc[2*ks+1][0] * inv0, sacc[2*ks+1][1] * inv0);
        __half2 ha3 = __floats2half2_rn(sacc[2*ks+1][2] * inv1, sacc[2*ks+1][3] * inv1);
        uint32_t a0 = *(uint32_t*)&ha0;
        uint32_t a1 = *(uint32_t*)&ha1;
        uint32_t a2 = *(uint32_t*)&ha2;
        uint32_t a3 = *(uint32_t*)&ha3;
        #pragma unroll
        for (int dt = 0; dt < 4; dt++) {
            uint32_t bf[4];
            int tr = ks * 16 + ((blk & 1) << 3) + rin;
            int dc = dt * 16 + ((blk >> 1) << 3);
            ldm4t(bf, sv + (tr * FLDV + dc) * 2);
            mma_fp16(yacc[dt*2  ], a0, a1, a2, a3, bf[0], bf[1]);
            mma_fp16(yacc[dt*2+1], a0, a1, a2, a3, bf[2], bf[3]);
        }
    }

    // ---- write y (fp32) ----
    #pragma unroll
    for (int nt = 0; nt < 8; nt++) {
        int col = h * HD + nt * 8 + 2 * tg;
        size_t row0 = (size_t)(b * TT + t0 + rb + g);
        *(float2*)(out + row0 * DD + col) = make_float2(yacc[nt][0], yacc[nt][1]);
        *(float2*)(out + (row0 + 8) * DD + col) = make_float2(yacc[nt][2], yacc[nt][3]);
    }
}

// ---------------- launch ----------------
extern "C" void kernel_launch(void* const* d_in, const int* in_sizes, int n_in,
                              void* d_out, int out_size) {
    const float* x     = (const float*)d_in[0];
    const float* xf    = (const float*)d_in[1];
    const float* ln_g  = (const float*)d_in[2];
    const float* ln_b  = (const float*)d_in[3];
    const float* tln_g = (const float*)d_in[4];
    const float* tln_b = (const float*)d_in[5];
    const float* Wq    = (const float*)d_in[6];
    const float* bq    = (const float*)d_in[7];
    const float* Wk    = (const float*)d_in[8];
    const float* bk    = (const float*)d_in[9];
    const float* Wv    = (const float*)d_in[10];
    const float* bv    = (const float*)d_in[11];
    float* out = (float*)d_out;

    void *p_xn, *p_xfn, *p_wqT, *p_wkT, *p_wvT, *p_k, *p_v;
    cudaGetSymbolAddress(&p_xn,  g_xn);
    cudaGetSymbolAddress(&p_xfn, g_xfn);
    cudaGetSymbolAddress(&p_wqT, g_wqT);
    cudaGetSymbolAddress(&p_wkT, g_wkT);
    cudaGetSymbolAddress(&p_wvT, g_wvT);
    cudaGetSymbolAddress(&p_k,   g_k);
    cudaGetSymbolAddress(&p_v,   g_v);

    cudaFuncSetAttribute(hgemm, cudaFuncAttributeMaxDynamicSharedMemorySize, GEMM_SMEM);
    cudaFuncSetAttribute(fused_qattn, cudaFuncAttributeMaxDynamicSharedMemorySize, FUSED_SMEM);

    // 1) prep: both LayerNorms + all three weight transposes
    prep_kernel<<<PREP_BLOCKS, 256>>>(x, xf, ln_g, ln_b, tln_g, tln_b, Wq, Wk, Wv);

    // 2) k,v = xfn @ {Wk,Wv} : 80 tiles each, one persistent launch
    hgemm<<<160, 256, GEMM_SMEM>>>(
        (const __half*)p_xfn, (const __half*)p_wkT, (const __half*)p_wvT,
        bk, bv, (__half*)p_k, (__half*)p_v,
        M_XF, LL, LL / GBK, 160, 80);

    // 3) fused q-GEMM + attention (q never materialized)
    fused_qattn<<<dim3(HH, TT / 128, BB), 256, FUSED_SMEM>>>(
        (const __half*)p_xn, (const __half*)p_wqT, bq,
        (const __half*)p_k, (const __half*)p_v, out);
}

// round 11
// speedup vs baseline: 2.9844x; 1.0822x over previous
#include <cuda_runtime.h>
#include <cuda_fp16.h>
#include <cstdint>
#include <cstddef>

// ---------------- problem constants ----------------
#define BB   32
#define TT   1024
#define NN   77
#define DD   512
#define LL   256
#define HH   8
#define HD   64
#define M_X  (BB*TT)          // 32768 rows of x
#define M_XF (BB*NN)          // 2464 rows of xf

// ---------------- scratch (static device, no allocation) ----------------
__device__ __half g_xn [(size_t)M_X * DD];    // 32 MB  LN(x) fp16
__device__ __half g_xfn[(size_t)M_XF * LL];
__device__ __half g_wqT[DD * DD];             // [N][K] fp16 (K-major)
__device__ __half g_wkT[DD * LL];
__device__ __half g_wvT[DD * LL];
__device__ __half g_k[(size_t)M_XF * DD];
__device__ __half g_v[(size_t)M_XF * DD];

// ---------------- primitives ----------------
__device__ __forceinline__ uint32_t smem_u32(const void* p) {
    return (uint32_t)__cvta_generic_to_shared(p);
}
__device__ __forceinline__ void mma_fp16(float* c,
                                         uint32_t a0, uint32_t a1, uint32_t a2, uint32_t a3,
                                         uint32_t b0, uint32_t b1) {
    asm volatile(
        "mma.sync.aligned.m16n8k16.row.col.f32.f16.f16.f32 "
        "{%0,%1,%2,%3}, {%4,%5,%6,%7}, {%8,%9}, {%0,%1,%2,%3};"
        : "+f"(c[0]), "+f"(c[1]), "+f"(c[2]), "+f"(c[3])
        : "r"(a0), "r"(a1), "r"(a2), "r"(a3), "r"(b0), "r"(b1));
}
__device__ __forceinline__ void ldm4(uint32_t* r, uint32_t addr) {
    asm volatile("ldmatrix.sync.aligned.m8n8.x4.shared.b16 {%0,%1,%2,%3}, [%4];"
                 : "=r"(r[0]), "=r"(r[1]), "=r"(r[2]), "=r"(r[3]) : "r"(addr));
}
__device__ __forceinline__ void ldm4t(uint32_t* r, uint32_t addr) {
    asm volatile("ldmatrix.sync.aligned.m8n8.x4.trans.shared.b16 {%0,%1,%2,%3}, [%4];"
                 : "=r"(r[0]), "=r"(r[1]), "=r"(r[2]), "=r"(r[3]) : "r"(addr));
}
__device__ __forceinline__ void cp_async16(uint32_t dst, const void* src) {
    asm volatile("cp.async.cg.shared.global [%0], [%1], 16;"
                 :: "r"(dst), "l"(src) : "memory");
}
__device__ __forceinline__ void cp_async16z(uint32_t dst, const void* src, int src_bytes) {
    asm volatile("cp.async.cg.shared.global [%0], [%1], 16, %2;"
                 :: "r"(dst), "l"(src), "r"(src_bytes) : "memory");
}

// ---------------- K1: prep = LN(x) + LN(xf) + 3 weight transposes ----------------
#define LN_X_BLOCKS   (M_X / 8)            // 4096
#define LN_XF_BLOCKS  (M_XF / 8)           // 308
#define WCONV_OFF     (LN_X_BLOCKS + LN_XF_BLOCKS)   // 4404
#define PREP_BLOCKS   (WCONV_OFF + 512)

__global__ __launch_bounds__(256) void prep_kernel(
    const float* __restrict__ x,  const float* __restrict__ xf,
    const float* __restrict__ ln_g,  const float* __restrict__ ln_b,
    const float* __restrict__ tln_g, const float* __restrict__ tln_b,
    const float* __restrict__ Wq, const float* __restrict__ Wk, const float* __restrict__ Wv)
{
    __shared__ float t[32][33];
    const int bid = blockIdx.x;
    const int tid = threadIdx.x;

    if (bid < WCONV_OFF) {
        const float* X;
        const float* gamma;
        const float* beta;
        __half* Y;
        int K, row;
        if (bid < LN_X_BLOCKS) {
            X = x; gamma = ln_g; beta = ln_b; Y = g_xn; K = DD;
            row = bid * 8 + (tid >> 5);
        } else {
            X = xf; gamma = tln_g; beta = tln_b; Y = g_xfn; K = LL;
            row = (bid - LN_X_BLOCKS) * 8 + (tid >> 5);
        }
        int lane = tid & 31;
        const float4* p = (const float4*)(X + (size_t)row * K);
        const int cnt = K >> 7;
        float4 v[4];
        float s = 0.f, sq = 0.f;
        #pragma unroll
        for (int j = 0; j < 4; j++) if (j < cnt) {
            v[j] = p[lane + 32 * j];
            s  += v[j].x + v[j].y + v[j].z + v[j].w;
            sq += v[j].x*v[j].x + v[j].y*v[j].y + v[j].z*v[j].z + v[j].w*v[j].w;
        }
        #pragma unroll
        for (int off = 16; off > 0; off >>= 1) {
            s  += __shfl_xor_sync(0xffffffffu, s,  off);
            sq += __shfl_xor_sync(0xffffffffu, sq, off);
        }
        float mean = s / (float)K;
        float var  = fmaxf(sq / (float)K - mean * mean, 0.f);
        float rstd = rsqrtf(var + 1e-5f);
        uint2* o = (uint2*)(Y + (size_t)row * K);
        #pragma unroll
        for (int j = 0; j < 4; j++) if (j < cnt) {
            int idx = lane + 32 * j;
            float4 g4 = ((const float4*)gamma)[idx];
            float4 b4 = ((const float4*)beta)[idx];
            __half2 h01 = __floats2half2_rn((v[j].x - mean) * rstd * g4.x + b4.x,
                                            (v[j].y - mean) * rstd * g4.y + b4.y);
            __half2 h23 = __floats2half2_rn((v[j].z - mean) * rstd * g4.z + b4.z,
                                            (v[j].w - mean) * rstd * g4.w + b4.w);
            uint2 u;
            u.x = *(uint32_t*)&h01;
            u.y = *(uint32_t*)&h23;
            o[idx] = u;
        }
    } else {
        int wt = bid - WCONV_OFF;
        const float* W;
        __half* WT;
        int K, nt, kt;
        if (wt < 256)      { W = Wq; WT = g_wqT; K = DD; nt = wt % 16;        kt = wt / 16; }
        else if (wt < 384) { W = Wk; WT = g_wkT; K = LL; nt = (wt-256) % 16;  kt = (wt-256) / 16; }
        else               { W = Wv; WT = g_wvT; K = LL; nt = (wt-384) % 16;  kt = (wt-384) / 16; }
        int nb = nt * 32, kb = kt * 32;
        int tx = tid & 31, ty = tid >> 5;
        for (int i = ty; i < 32; i += 8)
            t[i][tx] = W[(size_t)(kb + i) * DD + nb + tx];
        __syncthreads();
        for (int i = ty; i < 32; i += 8)
            WT[(size_t)(nb + i) * K + kb + tx] = __float2half_rn(t[tx][i]);
    }
}

// ---------------- K2: persistent fp16 tensor GEMM (k/v only) ----------------
#define GBK 64
#define A_BYTES 16384
#define STG_BYTES 32768
#define NSTG 3
#define GEMM_SMEM (NSTG * STG_BYTES)

__global__ __launch_bounds__(256, 2) void hgemm(
    const __half* __restrict__ A,
    const __half* __restrict__ BT0, const __half* __restrict__ BT1,
    const float* __restrict__ bias0, const float* __restrict__ bias1,
    __half* __restrict__ C0, __half* __restrict__ C1,
    int M, int K, int KT, int ntiles, int tiles_per_w)
{
    extern __shared__ char smraw[];
    const uint32_t sb = smem_u32(smraw);
    const int tid  = threadIdx.x;
    const int wid  = tid >> 5;
    const int lane = tid & 31;
    const int wm = wid & 3;
    const int wn = wid >> 2;
    const int g  = lane >> 2;
    const int tg = lane & 3;
    const int blk = lane >> 3;
    const int rin = lane & 7;
    const int G = (int)gridDim.x;

    int t_l = blockIdx.x, kt_l = 0;

    auto load_step = [&](int st) {
        if (t_l < ntiles) {
            int w = (t_l >= tiles_per_w) ? 1 : 0;
            int r = t_l - (w ? tiles_per_w : 0);
            int m0 = (r >> 2) * 128;
            int n0 = (r & 3) * 128;
            const __half* Bt = w ? BT1 : BT0;
            uint32_t base = sb + st * STG_BYTES;
            #pragma unroll
            for (int i = 0; i < 4; i++) {
                int id = tid + i * 256;
                int row = id >> 3, c = id & 7;
                int m = m0 + row;
                if (m >= M) m = M - 1;
                cp_async16(base + row * 128 + ((c ^ (row & 7)) << 4),
                           A + (size_t)m * K + kt_l * GBK + c * 8);
            }
            #pragma unroll
            for (int i = 0; i < 4; i++) {
                int id = tid + i * 256;
                int row = id >> 3, c = id & 7;
                cp_async16(base + A_BYTES + row * 128 + ((c ^ (row & 7)) << 4),
                           Bt + (size_t)(n0 + row) * K + kt_l * GBK + c * 8);
            }
        }
        asm volatile("cp.async.commit_group;" ::: "memory");
        if (++kt_l == KT) { kt_l = 0; t_l += G; }
    };

    float acc[2][8][4];
    #pragma unroll
    for (int mt = 0; mt < 2; mt++)
        #pragma unroll
        for (int nt = 0; nt < 8; nt++)
            #pragma unroll
            for (int j = 0; j < 4; j++) acc[mt][nt][j] = 0.f;

    load_step(0);
    load_step(1);

    int stage = 0;
    int t_c = blockIdx.x, kt_c = 0;

    while (t_c < ntiles) {
        asm volatile("cp.async.wait_group 1;" ::: "memory");
        __syncthreads();
        const uint32_t aB = sb + stage * STG_BYTES;
        const uint32_t bB = aB + A_BYTES;

        #pragma unroll
        for (int ks = 0; ks < 4; ks++) {
            uint32_t af[2][4];
            #pragma unroll
            for (int mt = 0; mt < 2; mt++) {
                int row = wm * 32 + mt * 16 + ((blk & 1) << 3) + rin;
                int ch  = 2 * ks + (blk >> 1);
                ldm4(af[mt], aB + row * 128 + ((ch ^ (row & 7)) << 4));
            }
            #pragma unroll
            for (int np = 0; np < 4; np++) {
                uint32_t bf[4];
                int nr = wn * 64 + np * 16 + ((blk >> 1) << 3) + rin;
                int ch = 2 * ks + (blk & 1);
                ldm4(bf, bB + nr * 128 + ((ch ^ (nr & 7)) << 4));
                mma_fp16(acc[0][np*2  ], af[0][0], af[0][1], af[0][2], af[0][3], bf[0], bf[1]);
                mma_fp16(acc[0][np*2+1], af[0][0], af[0][1], af[0][2], af[0][3], bf[2], bf[3]);
                mma_fp16(acc[1][np*2  ], af[1][0], af[1][1], af[1][2], af[1][3], bf[0], bf[1]);
                mma_fp16(acc[1][np*2+1], af[1][0], af[1][1], af[1][2], af[1][3], bf[2], bf[3]);
            }
        }

        int nst = stage + 2;
        if (nst >= NSTG) nst -= NSTG;
        load_step(nst);

        if (++kt_c == KT) {
            int w = (t_c >= tiles_per_w) ? 1 : 0;
            int r = t_c - (w ? tiles_per_w : 0);
            int m0 = (r >> 2) * 128;
            int n0 = (r & 3) * 128;
            const float* bias = w ? bias1 : bias0;
            __half* C = w ? C1 : C0;
            #pragma unroll
            for (int mt = 0; mt < 2; mt++) {
                int r0 = m0 + wm * 32 + mt * 16 + g;
                #pragma unroll
                for (int nt = 0; nt < 8; nt++) {
                    int col = n0 + wn * 64 + nt * 8 + 2 * tg;
                    float b0 = bias[col], b1 = bias[col + 1];
                    if (r0 < M) {
                        __half2 h = __floats2half2_rn(acc[mt][nt][0] + b0, acc[mt][nt][1] + b1);
                        *(uint32_t*)(C + (size_t)r0 * DD + col) = *(uint32_t*)&h;
                    }
                    if (r0 + 8 < M) {
                        __half2 h = __floats2half2_rn(acc[mt][nt][2] + b0, acc[mt][nt][3] + b1);
                        *(uint32_t*)(C + (size_t)(r0 + 8) * DD + col) = *(uint32_t*)&h;
                    }
                    acc[mt][nt][0] = 0.f; acc[mt][nt][1] = 0.f;
                    acc[mt][nt][2] = 0.f; acc[mt][nt][3] = 0.f;
                }
            }
            kt_c = 0;
            t_c += G;
        }
        if (++stage == NSTG) stage = 0;
    }
}

// ---------------- K3: fused qGEMM + attention, 3-stage pipeline ----------------
// grid (H, T/128, B) = (8, 8, 32); 256 threads, warp owns 16 t-rows.
// q computed in registers: stream xn/WqT k-chunks (3 buffers, ONE sync/chunk);
// q c-frag == S a-frag layout, P register-resident.
#define FLDX 72
#define FLDW 72
#define FLDK 72
#define FLDV 72
#define SX_BYTES (128 * FLDX * 2)         // 18432
#define SW_BYTES (64 * FLDW * 2)          // 9216
#define STG_F    (SX_BYTES + SW_BYTES)    // 27648 per stage
#define FNSTG    3
#define OFF_SK   (FNSTG * STG_F)          // 82944
#define OFF_SV   (OFF_SK + 80 * FLDK * 2) // 94464
#define FUSED_SMEM (OFF_SV + 80 * FLDV * 2)  // 105984

__global__ __launch_bounds__(256, 2) void fused_qattn(
    const __half* __restrict__ xn, const __half* __restrict__ wqT,
    const float* __restrict__ bq,
    const __half* __restrict__ k, const __half* __restrict__ v,
    float* __restrict__ out)
{
    extern __shared__ char smraw[];
    const uint32_t sb = smem_u32(smraw);
    const uint32_t sk = sb + OFF_SK;
    const uint32_t sv = sb + OFF_SV;

    const int h  = blockIdx.x;
    const int t0 = blockIdx.y * 128;
    const int b  = blockIdx.z;
    const int tid  = threadIdx.x;
    const int wid  = tid >> 5;
    const int lane = tid & 31;
    const int g  = lane >> 2;
    const int tg = lane & 3;
    const int blk = lane >> 3;
    const int rin = lane & 7;
    const int rb = wid * 16;
    const float scale = 0.125f;

    auto load_chunk = [&](int st, int kt) {
        uint32_t xb = sb + st * STG_F;
        #pragma unroll
        for (int i = 0; i < 4; i++) {
            int id = tid + i * 256;
            int r = id >> 3, c = id & 7;
            cp_async16(xb + (r * FLDX + c * 8) * 2,
                       xn + (size_t)(b * TT + t0 + r) * DD + kt * 64 + c * 8);
        }
        uint32_t wb = xb + SX_BYTES;
        #pragma unroll
        for (int i = 0; i < 2; i++) {
            int id = tid + i * 256;
            int r = id >> 3, c = id & 7;
            cp_async16(wb + (r * FLDW + c * 8) * 2,
                       wqT + (size_t)(h * HD + r) * DD + kt * 64 + c * 8);
        }
    };

    // ---- prologue: kv + chunk0 in group0, chunk1 in group1 ----
    for (int s = tid; s < 80 * 8; s += 256) {
        int n = s >> 3, c = s & 7;
        int ok = (n < NN) ? 16 : 0;
        size_t base = (size_t)(b * NN + ((n < NN) ? n : 0)) * DD + h * HD + c * 8;
        cp_async16z(sk + (n * FLDK + c * 8) * 2, k + base, ok);
        cp_async16z(sv + (n * FLDV + c * 8) * 2, v + base, ok);
    }
    load_chunk(0, 0);
    asm volatile("cp.async.commit_group;" ::: "memory");
    load_chunk(1, 1);
    asm volatile("cp.async.commit_group;" ::: "memory");

    // ---- q = xn @ WqT^T : warp computes rows rb..rb+15 x 64 cols, K=512 ----
    // 3-stage pipeline, ONE __syncthreads per chunk (hgemm pattern).
    float qacc[8][4];
    #pragma unroll
    for (int nt = 0; nt < 8; nt++)
        #pragma unroll
        for (int j = 0; j < 4; j++) qacc[nt][j] = 0.f;

    int stage = 0;
    for (int kt = 0; kt < 8; kt++) {
        asm volatile("cp.async.wait_group 1;" ::: "memory");
        __syncthreads();
        const uint32_t xb = sb + stage * STG_F;
        const uint32_t wb = xb + SX_BYTES;
        #pragma unroll
        for (int ks = 0; ks < 4; ks++) {
            uint32_t af[4];
            {
                int row = rb + ((blk & 1) << 3) + rin;
                int col = ks * 16 + ((blk >> 1) << 3);
                ldm4(af, xb + (row * FLDX + col) * 2);
            }
            #pragma unroll
            for (int np = 0; np < 4; np++) {
                uint32_t bf[4];
                int nr = np * 16 + ((blk >> 1) << 3) + rin;
                int bc = ks * 16 + ((blk & 1) << 3);
                ldm4(bf, wb + (nr * FLDW + bc) * 2);
                mma_fp16(qacc[np*2  ], af[0], af[1], af[2], af[3], bf[0], bf[1]);
                mma_fp16(qacc[np*2+1], af[0], af[1], af[2], af[3], bf[2], bf[3]);
            }
        }
        // prefetch chunk kt+2 into stage (stage+2)%3 (consumed at iter kt-1; safe past this iter's sync)
        int nst = stage + 2;
        if (nst >= FNSTG) nst -= FNSTG;
        if (kt + 2 < 8) load_chunk(nst, kt + 2);
        asm volatile("cp.async.commit_group;" ::: "memory");
        if (++stage == FNSTG) stage = 0;
    }

    // ---- + bias, fold softmax scale, pack q into a-frags ----
    uint32_t qa[4][4];
    #pragma unroll
    for (int nt = 0; nt < 8; nt++) {
        int col = h * HD + nt * 8 + 2 * tg;
        float b0 = bq[col], b1 = bq[col + 1];
        qacc[nt][0] = (qacc[nt][0] + b0) * scale;
        qacc[nt][1] = (qacc[nt][1] + b1) * scale;
        qacc[nt][2] = (qacc[nt][2] + b0) * scale;
        qacc[nt][3] = (qacc[nt][3] + b1) * scale;
    }
    #pragma unroll
    for (int ks = 0; ks < 4; ks++) {
        __half2 a0 = __floats2half2_rn(qacc[2*ks  ][0], qacc[2*ks  ][1]);
        __half2 a1 = __floats2half2_rn(qacc[2*ks  ][2], qacc[2*ks  ][3]);
        __half2 a2 = __floats2half2_rn(qacc[2*ks+1][0], qacc[2*ks+1][1]);
        __half2 a3 = __floats2half2_rn(qacc[2*ks+1][2], qacc[2*ks+1][3]);
        qa[ks][0] = *(uint32_t*)&a0;
        qa[ks][1] = *(uint32_t*)&a1;
        qa[ks][2] = *(uint32_t*)&a2;
        qa[ks][3] = *(uint32_t*)&a3;
    }

    // ---- S = q @ k^T : 16 x 80 per warp ----
    float sacc[10][4];
    #pragma unroll
    for (int nt = 0; nt < 10; nt++)
        #pragma unroll
        for (int j = 0; j < 4; j++) sacc[nt][j] = 0.f;

    #pragma unroll
    for (int ks = 0; ks < 4; ks++) {
        #pragma unroll
        for (int nt16 = 0; nt16 < 5; nt16++) {
            uint32_t bf[4];
            int nr  = nt16 * 16 + ((blk >> 1) << 3) + rin;
            int col = ks * 16 + ((blk & 1) << 3);
            ldm4(bf, sk + (nr * FLDK + col) * 2);
            mma_fp16(sacc[nt16*2  ], qa[ks][0], qa[ks][1], qa[ks][2], qa[ks][3], bf[0], bf[1]);
            mma_fp16(sacc[nt16*2+1], qa[ks][0], qa[ks][1], qa[ks][2], qa[ks][3], bf[2], bf[3]);
        }
    }

    // ---- masked softmax over tokens (cols >= 77 masked; scale already folded) ----
    float mx0 = -1e30f, mx1 = -1e30f;
    #pragma unroll
    for (int nt = 0; nt < 10; nt++) {
        int c0 = nt * 8 + 2 * tg;
        if (c0     >= NN) { sacc[nt][0] = -1e30f; sacc[nt][2] = -1e30f; }
        if (c0 + 1 >= NN) { sacc[nt][1] = -1e30f; sacc[nt][3] = -1e30f; }
        mx0 = fmaxf(mx0, fmaxf(sacc[nt][0], sacc[nt][1]));
        mx1 = fmaxf(mx1, fmaxf(sacc[nt][2], sacc[nt][3]));
    }
    mx0 = fmaxf(mx0, __shfl_xor_sync(0xffffffffu, mx0, 1));
    mx0 = fmaxf(mx0, __shfl_xor_sync(0xffffffffu, mx0, 2));
    mx1 = fmaxf(mx1, __shfl_xor_sync(0xffffffffu, mx1, 1));
    mx1 = fmaxf(mx1, __shfl_xor_sync(0xffffffffu, mx1, 2));

    float s0 = 0.f, s1 = 0.f;
    #pragma unroll
    for (int nt = 0; nt < 10; nt++) {
        sacc[nt][0] = __expf(sacc[nt][0] - mx0);
        sacc[nt][1] = __expf(sacc[nt][1] - mx0);
        sacc[nt][2] = __expf(sacc[nt][2] - mx1);
        sacc[nt][3] = __expf(sacc[nt][3] - mx1);
        s0 += sacc[nt][0] + sacc[nt][1];
        s1 += sacc[nt][2] + sacc[nt][3];
    }
    s0 += __shfl_xor_sync(0xffffffffu, s0, 1);
    s0 += __shfl_xor_sync(0xffffffffu, s0, 2);
    s1 += __shfl_xor_sync(0xffffffffu, s1, 1);
    s1 += __shfl_xor_sync(0xffffffffu, s1, 2);
    const float inv0 = 1.0f / s0;
    const float inv1 = 1.0f / s1;

    // ---- Y = P @ V : P register-resident ----
    float yacc[8][4];
    #pragma unroll
    for (int nt = 0; nt < 8; nt++)
        #pragma unroll
        for (int j = 0; j < 4; j++) yacc[nt][j] = 0.f;

    #pragma unroll
    for (int ks = 0; ks < 5; ks++) {
        __half2 ha0 = __floats2half2_rn(sacc[2*ks  ][0] * inv0, sacc[2*ks  ][1] * inv0);
        __half2 ha1 = __floats2half2_rn(sacc[2*ks  ][2] * inv1, sacc[2*ks  ][3] * inv1);
        __half2 ha2 = __floats2half2_rn(sacc[2*ks+1][0] * inv0, sacc[2*ks+1][1] * inv0);
        __half2 ha3 = __floats2half2_rn(sacc[2*ks+1][2] * inv1, sacc[2*ks+1][3] * inv1);
        uint32_t a0 = *(uint32_t*)&ha0;
        uint32_t a1 = *(uint32_t*)&ha1;
        uint32_t a2 = *(uint32_t*)&ha2;
        uint32_t a3 = *(uint32_t*)&ha3;
        #pragma unroll
        for (int dt = 0; dt < 4; dt++) {
            uint32_t bf[4];
            int tr = ks * 16 + ((blk & 1) << 3) + rin;
            int dc = dt * 16 + ((blk >> 1) << 3);
            ldm4t(bf, sv + (tr * FLDV + dc) * 2);
            mma_fp16(yacc[dt*2  ], a0, a1, a2, a3, bf[0], bf[1]);
            mma_fp16(yacc[dt*2+1], a0, a1, a2, a3, bf[2], bf[3]);
        }
    }

    // ---- write y (fp32) ----
    #pragma unroll
    for (int nt = 0; nt < 8; nt++) {
        int col = h * HD + nt * 8 + 2 * tg;
        size_t row0 = (size_t)(b * TT + t0 + rb + g);
        *(float2*)(out + row0 * DD + col) = make_float2(yacc[nt][0], yacc[nt][1]);
        *(float2*)(out + (row0 + 8) * DD + col) = make_float2(yacc[nt][2], yacc[nt][3]);
    }
}

// ---------------- launch ----------------
extern "C" void kernel_launch(void* const* d_in, const int* in_sizes, int n_in,
                              void* d_out, int out_size) {
    const float* x     = (const float*)d_in[0];
    const float* xf    = (const float*)d_in[1];
    const float* ln_g  = (const float*)d_in[2];
    const float* ln_b  = (const float*)d_in[3];
    const float* tln_g = (const float*)d_in[4];
    const float* tln_b = (const float*)d_in[5];
    const float* Wq    = (const float*)d_in[6];
    const float* bq    = (const float*)d_in[7];
    const float* Wk    = (const float*)d_in[8];
    const float* bk    = (const float*)d_in[9];
    const float* Wv    = (const float*)d_in[10];
    const float* bv    = (const float*)d_in[11];
    float* out = (float*)d_out;

    void *p_xn, *p_xfn, *p_wqT, *p_wkT, *p_wvT, *p_k, *p_v;
    cudaGetSymbolAddress(&p_xn,  g_xn);
    cudaGetSymbolAddress(&p_xfn, g_xfn);
    cudaGetSymbolAddress(&p_wqT, g_wqT);
    cudaGetSymbolAddress(&p_wkT, g_wkT);
    cudaGetSymbolAddress(&p_wvT, g_wvT);
    cudaGetSymbolAddress(&p_k,   g_k);
    cudaGetSymbolAddress(&p_v,   g_v);

    cudaFuncSetAttribute(hgemm, cudaFuncAttributeMaxDynamicSharedMemorySize, GEMM_SMEM);
    cudaFuncSetAttribute(fused_qattn, cudaFuncAttributeMaxDynamicSharedMemorySize, FUSED_SMEM);

    // 1) prep: both LayerNorms + all three weight transposes
    prep_kernel<<<PREP_BLOCKS, 256>>>(x, xf, ln_g, ln_b, tln_g, tln_b, Wq, Wk, Wv);

    // 2) k,v = xfn @ {Wk,Wv} : 80 tiles each, one persistent launch
    hgemm<<<160, 256, GEMM_SMEM>>>(
        (const __half*)p_xfn, (const __half*)p_wkT, (const __half*)p_wvT,
        bk, bv, (__half*)p_k, (__half*)p_v,
        M_XF, LL, LL / GBK, 160, 80);

    // 3) fused q-GEMM + attention (q never materialized)
    fused_qattn<<<dim3(HH, TT / 128, BB), 256, FUSED_SMEM>>>(
        (const __half*)p_xn, (const __half*)p_wqT, bq,
        (const __half*)p_k, (const __half*)p_v, out);
}